// round 1
// baseline (speedup 1.0000x reference)
#include <cuda_runtime.h>

#define NN   100000   // nodes
#define NE   200000   // hyperedges
#define NNZV 800000   // pins
#define D    128
#define P    32

// ---------------- scratch (device globals; no allocation allowed) -----------
__device__ float g_efeat[(size_t)NE * D];   // edge accumulators (102.4 MB)
__device__ float g_agg[(size_t)NN * D];     // node accumulators (51.2 MB)
__device__ float g_h1[(size_t)NN * D];      // hconv1 output
__device__ float g_h2[(size_t)NN * D];      // hconv2 output
__device__ float g_t[(size_t)NN * D];       // MLP hidden
__device__ int   g_ecnt[NE];
__device__ int   g_ncnt[NN];
__device__ float g_einv[NE];
__device__ float g_ninv[NN];

// ---------------- small helpers ---------------------------------------------
__device__ __forceinline__ void red_add_v4(float* dst, float4 v) {
    asm volatile("red.global.add.v4.f32 [%0], {%1,%2,%3,%4};"
                 :: "l"(dst), "f"(v.x), "f"(v.y), "f"(v.z), "f"(v.w)
                 : "memory");
}

// ---------------- counts ------------------------------------------------------
__global__ void zero_counts_kernel() {
    int i = blockIdx.x * blockDim.x + threadIdx.x;
    int stride = gridDim.x * blockDim.x;
    for (int t = i; t < NE; t += stride) g_ecnt[t] = 0;
    for (int t = i; t < NN; t += stride) g_ncnt[t] = 0;
}

__global__ void count_kernel(const int* __restrict__ ni, const int* __restrict__ ei) {
    int t = blockIdx.x * blockDim.x + threadIdx.x;
    if (t < NNZV) {
        atomicAdd(&g_ecnt[ei[t]], 1);
        atomicAdd(&g_ncnt[ni[t]], 1);
    }
}

__global__ void inv_kernel() {
    int t = blockIdx.x * blockDim.x + threadIdx.x;
    if (t < NE) g_einv[t] = 1.0f / (float)max(g_ecnt[t], 1);
    if (t < NN) g_ninv[t] = 1.0f / (float)max(g_ncnt[t], 1);
}

__global__ void zero_scratch_kernel() {
    const int n4e = NE * (D / 4), n4n = NN * (D / 4);
    float4 z = make_float4(0.f, 0.f, 0.f, 0.f);
    int i = blockIdx.x * blockDim.x + threadIdx.x;
    int stride = gridDim.x * blockDim.x;
    float4* e4 = (float4*)g_efeat;
    float4* a4 = (float4*)g_agg;
    for (int t = i; t < n4e; t += stride) e4[t] = z;
    for (int t = i; t < n4n; t += stride) a4[t] = z;
}

// ---------------- scatter phases ---------------------------------------------
// One warp per pin; lane c handles float4 chunk c of the 128-wide row.
__global__ void __launch_bounds__(256)
scatter_edges_kernel(const float* __restrict__ xin,
                     const int* __restrict__ ni, const int* __restrict__ ei) {
    int t = blockIdx.x * 256 + threadIdx.x;
    int p = t >> 5;
    if (p >= NNZV) return;
    int c = t & 31;
    int node = __ldg(&ni[p]);
    int e    = __ldg(&ei[p]);
    float4 v = __ldg(&((const float4*)xin)[(size_t)node * (D / 4) + c]);
    red_add_v4(&g_efeat[(size_t)e * D + c * 4], v);
}

// gather edge accumulator, scale by 1/edge_count (fold edge mean), reduce to node
__global__ void __launch_bounds__(256)
scatter_nodes_kernel(const int* __restrict__ ni, const int* __restrict__ ei) {
    int t = blockIdx.x * 256 + threadIdx.x;
    int p = t >> 5;
    if (p >= NNZV) return;
    int c = t & 31;
    int node = __ldg(&ni[p]);
    int e    = __ldg(&ei[p]);
    float s  = __ldg(&g_einv[e]);
    float4 v = ((const float4*)g_efeat)[(size_t)e * (D / 4) + c];
    v.x *= s; v.y *= s; v.z *= s; v.w *= s;
    red_add_v4(&g_agg[(size_t)node * D + c * 4], v);
}

// ---------------- dense 128x128 GEMM + bias + ReLU ---------------------------
// out[r][j] = relu( sum_k (in[r][k] * rscale[r]) * W[k][j] + b[j] )
// Block: 256 threads, tile 128 rows x 128 cols, thread tile 8x8.
#define IS_STRIDE 130
#define GEMM_SMEM_BYTES ((128 * 128 + 128 * IS_STRIDE) * 4)

__global__ void __launch_bounds__(256)
gemm128_relu_kernel(const float* __restrict__ in, const float* __restrict__ rscale,
                    const float* __restrict__ W, const float* __restrict__ b,
                    float* __restrict__ out, int nrows) {
    extern __shared__ float sm[];
    float* Ws = sm;                 // [128][128]
    float* Is = sm + 128 * 128;     // [128][IS_STRIDE]
    const int tid = threadIdx.x;

    // load full W (64 KB)
    const float4* W4 = (const float4*)W;
    float4* Ws4 = (float4*)Ws;
    for (int i = tid; i < 128 * 32; i += 256) Ws4[i] = W4[i];

    // load input tile (with optional per-row scale fold)
    int row0 = blockIdx.x * 128;
    for (int i = tid; i < 128 * 32; i += 256) {
        int rl = i >> 5, c4 = i & 31;
        int r = row0 + rl;
        float4 v = make_float4(0.f, 0.f, 0.f, 0.f);
        if (r < nrows) {
            v = __ldg(&((const float4*)in)[(size_t)r * 32 + c4]);
            if (rscale) {
                float s = __ldg(&rscale[r]);
                v.x *= s; v.y *= s; v.z *= s; v.w *= s;
            }
        }
        float* dst = &Is[rl * IS_STRIDE + c4 * 4];
        dst[0] = v.x; dst[1] = v.y; dst[2] = v.z; dst[3] = v.w;
    }
    __syncthreads();

    const int ty = tid >> 4, tx = tid & 15;
    const int r0 = ty * 8, c0 = tx * 8;
    float acc[8][8];
#pragma unroll
    for (int i = 0; i < 8; i++)
#pragma unroll
        for (int j = 0; j < 8; j++) acc[i][j] = 0.f;

#pragma unroll 4
    for (int k = 0; k < 128; k++) {
        float a[8];
#pragma unroll
        for (int i = 0; i < 8; i++) a[i] = Is[(r0 + i) * IS_STRIDE + k];
        float4 w0 = *(const float4*)&Ws[k * 128 + c0];
        float4 w1 = *(const float4*)&Ws[k * 128 + c0 + 4];
#pragma unroll
        for (int i = 0; i < 8; i++) {
            acc[i][0] = fmaf(a[i], w0.x, acc[i][0]);
            acc[i][1] = fmaf(a[i], w0.y, acc[i][1]);
            acc[i][2] = fmaf(a[i], w0.z, acc[i][2]);
            acc[i][3] = fmaf(a[i], w0.w, acc[i][3]);
            acc[i][4] = fmaf(a[i], w1.x, acc[i][4]);
            acc[i][5] = fmaf(a[i], w1.y, acc[i][5]);
            acc[i][6] = fmaf(a[i], w1.z, acc[i][6]);
            acc[i][7] = fmaf(a[i], w1.w, acc[i][7]);
        }
    }

    float4 b0 = __ldg((const float4*)&b[c0]);
    float4 b1 = __ldg((const float4*)&b[c0 + 4]);
#pragma unroll
    for (int i = 0; i < 8; i++) {
        int r = row0 + r0 + i;
        if (r < nrows) {
            float4 s0 = make_float4(fmaxf(acc[i][0] + b0.x, 0.f),
                                    fmaxf(acc[i][1] + b0.y, 0.f),
                                    fmaxf(acc[i][2] + b0.z, 0.f),
                                    fmaxf(acc[i][3] + b0.w, 0.f));
            float4 s1 = make_float4(fmaxf(acc[i][4] + b1.x, 0.f),
                                    fmaxf(acc[i][5] + b1.y, 0.f),
                                    fmaxf(acc[i][6] + b1.z, 0.f),
                                    fmaxf(acc[i][7] + b1.w, 0.f));
            *(float4*)&out[(size_t)r * 128 + c0]     = s0;
            *(float4*)&out[(size_t)r * 128 + c0 + 4] = s1;
        }
    }
}

// ---------------- final 128->32 GEMM + softmax (warp per row) ----------------
__global__ void __launch_bounds__(256)
mlp2_softmax_kernel(const float* __restrict__ tin, const float* __restrict__ Wm2,
                    const float* __restrict__ bm2, float* __restrict__ out) {
    __shared__ float Ws[D * P];   // 16 KB
    __shared__ float bs[P];
    for (int i = threadIdx.x; i < D * P; i += blockDim.x) Ws[i] = Wm2[i];
    if (threadIdx.x < P) bs[threadIdx.x] = bm2[threadIdx.x];
    __syncthreads();

    int warp = threadIdx.x >> 5, lane = threadIdx.x & 31;
    int wpb = blockDim.x >> 5;
    for (int row = blockIdx.x * wpb + warp; row < NN; row += gridDim.x * wpb) {
        float4 a = __ldg(&((const float4*)tin)[(size_t)row * 32 + lane]);
        float av[4] = {a.x, a.y, a.z, a.w};
        float acc = bs[lane];
#pragma unroll
        for (int k = 0; k < 128; k++) {
            float xk = __shfl_sync(0xffffffffu, av[k & 3], k >> 2);
            acc = fmaf(xk, Ws[k * P + lane], acc);
        }
        // softmax over 32 lanes
        float m = acc;
#pragma unroll
        for (int o = 16; o; o >>= 1) m = fmaxf(m, __shfl_xor_sync(0xffffffffu, m, o));
        float e = expf(acc - m);
        float s = e;
#pragma unroll
        for (int o = 16; o; o >>= 1) s += __shfl_xor_sync(0xffffffffu, s, o);
        out[(size_t)row * P + lane] = e / s;
    }
}

// ---------------- launch ------------------------------------------------------
extern "C" void kernel_launch(void* const* d_in, const int* in_sizes, int n_in,
                              void* d_out, int out_size) {
    const float* x   = (const float*)d_in[0];
    const int*   ni  = (const int*)  d_in[1];
    const int*   ei  = (const int*)  d_in[2];
    const float* W1  = (const float*)d_in[3];
    const float* b1  = (const float*)d_in[4];
    const float* W2  = (const float*)d_in[5];
    const float* b2  = (const float*)d_in[6];
    const float* Wm1 = (const float*)d_in[7];
    const float* bm1 = (const float*)d_in[8];
    const float* Wm2 = (const float*)d_in[9];
    const float* bm2 = (const float*)d_in[10];
    float* out = (float*)d_out;

    cudaFuncSetAttribute(gemm128_relu_kernel,
                         cudaFuncAttributeMaxDynamicSharedMemorySize,
                         GEMM_SMEM_BYTES);

    // pointers to scratch (for kernels that take them as args)
    float* efeat; cudaGetSymbolAddress((void**)&efeat, g_efeat);
    float* agg;   cudaGetSymbolAddress((void**)&agg,   g_agg);
    float* h1;    cudaGetSymbolAddress((void**)&h1,    g_h1);
    float* h2;    cudaGetSymbolAddress((void**)&h2,    g_h2);
    float* tbuf;  cudaGetSymbolAddress((void**)&tbuf,  g_t);
    float* ninv;  cudaGetSymbolAddress((void**)&ninv,  g_ninv);
    (void)efeat; (void)in_sizes; (void)n_in; (void)out_size;

    const int scatter_blocks = (NNZV * 32) / 256;   // 100000

    // counts (recomputed each call; deterministic, cheap)
    zero_counts_kernel<<<512, 256>>>();
    count_kernel<<<(NNZV + 255) / 256, 256>>>(ni, ei);
    inv_kernel<<<(NE + 255) / 256, 256>>>();

    // ---- hconv layer 1: x -> h1 ----
    zero_scratch_kernel<<<2048, 256>>>();
    scatter_edges_kernel<<<scatter_blocks, 256>>>(x, ni, ei);
    scatter_nodes_kernel<<<scatter_blocks, 256>>>(ni, ei);
    gemm128_relu_kernel<<<(NN + 127) / 128, 256, GEMM_SMEM_BYTES>>>(
        agg, ninv, W1, b1, h1, NN);

    // ---- hconv layer 2: h1 -> h2 ----
    zero_scratch_kernel<<<2048, 256>>>();
    scatter_edges_kernel<<<scatter_blocks, 256>>>(h1, ni, ei);
    scatter_nodes_kernel<<<scatter_blocks, 256>>>(ni, ei);
    gemm128_relu_kernel<<<(NN + 127) / 128, 256, GEMM_SMEM_BYTES>>>(
        agg, ninv, W2, b2, h2, NN);

    // ---- MLP hidden: h2 -> t ----
    gemm128_relu_kernel<<<(NN + 127) / 128, 256, GEMM_SMEM_BYTES>>>(
        h2, nullptr, Wm1, bm1, tbuf, NN);

    // ---- logits + softmax -> out ----
    mlp2_softmax_kernel<<<2048, 256>>>(tbuf, Wm2, bm2, out);
}

// round 3
// speedup vs baseline: 1.2676x; 1.2676x over previous
#include <cuda_runtime.h>

#define NN   100000   // nodes
#define NE   200000   // hyperedges
#define NNZV 800000   // pins
#define D    128
#define P    32

#define EBLK ((NE + 1023) / 1024)   // 196 scan blocks for edges
#define NBLK ((NN + 1023) / 1024)   // 98 scan blocks for nodes

// ---------------- scratch (device globals; no allocation allowed) -----------
__device__ float g_efeat[(size_t)NE * D];   // edge means (102.4 MB)
__device__ float g_agg[(size_t)NN * D];     // node means (51.2 MB)
__device__ float g_h1[(size_t)NN * D];      // hconv1 output
__device__ float g_h2[(size_t)NN * D];      // hconv2 output
__device__ float g_t[(size_t)NN * D];       // MLP hidden
__device__ int   g_ecnt[NE];
__device__ int   g_ncnt[NN];
__device__ int   g_eoff[NE];
__device__ int   g_noff[NN];
__device__ int   g_ecur[NE];
__device__ int   g_ncur[NN];
__device__ int   g_epins[NNZV];             // node ids grouped by edge
__device__ int   g_npins[NNZV];             // edge ids grouped by node
__device__ int   g_esums[256];
__device__ int   g_nsums[256];

// ---------------- CSR build ---------------------------------------------------
__global__ void zero_counts_kernel() {
    int i = blockIdx.x * blockDim.x + threadIdx.x;
    int stride = gridDim.x * blockDim.x;
    for (int t = i; t < NE; t += stride) g_ecnt[t] = 0;
    for (int t = i; t < NN; t += stride) g_ncnt[t] = 0;
}

__global__ void count_kernel(const int* __restrict__ ni, const int* __restrict__ ei) {
    int t = blockIdx.x * blockDim.x + threadIdx.x;
    if (t < NNZV) {
        atomicAdd(&g_ecnt[ei[t]], 1);
        atomicAdd(&g_ncnt[ni[t]], 1);
    }
}

// Each block scans 1024 elements (4/thread). Writes exclusive per-element
// offsets (block-local) and the block total into sums[blockIdx.x].
__global__ void __launch_bounds__(256)
scan_block_kernel(const int* __restrict__ cnt, int n,
                  int* __restrict__ out, int* __restrict__ sums) {
    __shared__ int sm[256];
    int tid = threadIdx.x;
    int base = blockIdx.x * 1024 + tid * 4;
    int v[4]; int s = 0;
#pragma unroll
    for (int i = 0; i < 4; i++) {
        int idx = base + i;
        v[i] = (idx < n) ? cnt[idx] : 0;
        s += v[i];
    }
    sm[tid] = s; __syncthreads();
    for (int off = 1; off < 256; off <<= 1) {
        int u = (tid >= off) ? sm[tid - off] : 0;
        __syncthreads();
        sm[tid] += u;
        __syncthreads();
    }
    int excl = sm[tid] - s;
    if (tid == 255) sums[blockIdx.x] = sm[255];
    int run = excl;
#pragma unroll
    for (int i = 0; i < 4; i++) {
        int idx = base + i;
        if (idx < n) out[idx] = run;
        run += v[i];
    }
}

// Single launch, 2 blocks: block 0 scans edge partials, block 1 node partials.
__global__ void __launch_bounds__(256) scan_sums_kernel() {
    int* sums = (blockIdx.x == 0) ? g_esums : g_nsums;
    int nb    = (blockIdx.x == 0) ? EBLK : NBLK;
    __shared__ int sm[256];
    int tid = threadIdx.x;
    int s = (tid < nb) ? sums[tid] : 0;
    sm[tid] = s; __syncthreads();
    for (int off = 1; off < 256; off <<= 1) {
        int u = (tid >= off) ? sm[tid - off] : 0;
        __syncthreads();
        sm[tid] += u;
        __syncthreads();
    }
    sums[tid] = sm[tid];   // inclusive scan of block totals
}

__global__ void scan_add_kernel(int* __restrict__ offp, int* __restrict__ cur,
                                const int* __restrict__ sums, int n) {
    int idx = blockIdx.x * blockDim.x + threadIdx.x;
    if (idx < n) {
        int b = idx >> 10;
        int add = (b > 0) ? sums[b - 1] : 0;
        int v = offp[idx] + add;
        offp[idx] = v;
        cur[idx] = v;
    }
}

__global__ void fill_kernel(const int* __restrict__ ni, const int* __restrict__ ei) {
    int t = blockIdx.x * blockDim.x + threadIdx.x;
    if (t < NNZV) {
        int n = ni[t], e = ei[t];
        g_epins[atomicAdd(&g_ecur[e], 1)] = n;
        g_npins[atomicAdd(&g_ncur[n], 1)] = e;
    }
}

// ---------------- segment-mean gather (warp per segment) ---------------------
// dst[seg] = mean over pins of src rows. Lanes hold float4 chunks of a 128-wide
// row; pin indices loaded coalesced 32 at a time, broadcast via shfl.
__global__ void __launch_bounds__(256)
seg_mean_gather_kernel(const float* __restrict__ src, float* __restrict__ dst,
                       const int* __restrict__ offs, const int* __restrict__ cnts,
                       const int* __restrict__ pins, int nseg) {
    int w = blockIdx.x * 8 + (threadIdx.x >> 5);
    if (w >= nseg) return;
    int lane = threadIdx.x & 31;
    int off = __ldg(&offs[w]);
    int deg = __ldg(&cnts[w]);
    const float4* s4 = (const float4*)src;
    float4 acc = make_float4(0.f, 0.f, 0.f, 0.f);
    for (int j = 0; j < deg; j += 32) {
        int rem = deg - j;
        int idx = (lane < rem) ? __ldg(&pins[off + j + lane]) : 0;
        int kmax = rem < 32 ? rem : 32;
        for (int k = 0; k < kmax; k++) {
            int r = __shfl_sync(0xffffffffu, idx, k);
            float4 v = __ldg(&s4[(size_t)r * 32 + lane]);
            acc.x += v.x; acc.y += v.y; acc.z += v.z; acc.w += v.w;
        }
    }
    float sc = 1.0f / (float)(deg > 0 ? deg : 1);
    acc.x *= sc; acc.y *= sc; acc.z *= sc; acc.w *= sc;
    ((float4*)dst)[(size_t)w * 32 + lane] = acc;
}

// ---------------- dense 128x128 GEMM + bias + ReLU ---------------------------
#define IS_STRIDE 130
#define GEMM_SMEM_BYTES ((128 * 128 + 128 * IS_STRIDE) * 4)

__global__ void __launch_bounds__(256)
gemm128_relu_kernel(const float* __restrict__ in,
                    const float* __restrict__ W, const float* __restrict__ b,
                    float* __restrict__ out, int nrows) {
    extern __shared__ float sm[];
    float* Ws = sm;                 // [128][128]
    float* Is = sm + 128 * 128;     // [128][IS_STRIDE]
    const int tid = threadIdx.x;

    const float4* W4 = (const float4*)W;
    float4* Ws4 = (float4*)Ws;
    for (int i = tid; i < 128 * 32; i += 256) Ws4[i] = W4[i];

    int row0 = blockIdx.x * 128;
    for (int i = tid; i < 128 * 32; i += 256) {
        int rl = i >> 5, c4 = i & 31;
        int r = row0 + rl;
        float4 v = make_float4(0.f, 0.f, 0.f, 0.f);
        if (r < nrows) v = __ldg(&((const float4*)in)[(size_t)r * 32 + c4]);
        float* dst = &Is[rl * IS_STRIDE + c4 * 4];
        dst[0] = v.x; dst[1] = v.y; dst[2] = v.z; dst[3] = v.w;
    }
    __syncthreads();

    const int ty = tid >> 4, tx = tid & 15;
    const int r0 = ty * 8, c0 = tx * 8;
    float acc[8][8];
#pragma unroll
    for (int i = 0; i < 8; i++)
#pragma unroll
        for (int j = 0; j < 8; j++) acc[i][j] = 0.f;

#pragma unroll 4
    for (int k = 0; k < 128; k++) {
        float a[8];
#pragma unroll
        for (int i = 0; i < 8; i++) a[i] = Is[(r0 + i) * IS_STRIDE + k];
        float4 w0 = *(const float4*)&Ws[k * 128 + c0];
        float4 w1 = *(const float4*)&Ws[k * 128 + c0 + 4];
#pragma unroll
        for (int i = 0; i < 8; i++) {
            acc[i][0] = fmaf(a[i], w0.x, acc[i][0]);
            acc[i][1] = fmaf(a[i], w0.y, acc[i][1]);
            acc[i][2] = fmaf(a[i], w0.z, acc[i][2]);
            acc[i][3] = fmaf(a[i], w0.w, acc[i][3]);
            acc[i][4] = fmaf(a[i], w1.x, acc[i][4]);
            acc[i][5] = fmaf(a[i], w1.y, acc[i][5]);
            acc[i][6] = fmaf(a[i], w1.z, acc[i][6]);
            acc[i][7] = fmaf(a[i], w1.w, acc[i][7]);
        }
    }

    float4 b0 = __ldg((const float4*)&b[c0]);
    float4 b1 = __ldg((const float4*)&b[c0 + 4]);
#pragma unroll
    for (int i = 0; i < 8; i++) {
        int r = row0 + r0 + i;
        if (r < nrows) {
            float4 s0 = make_float4(fmaxf(acc[i][0] + b0.x, 0.f),
                                    fmaxf(acc[i][1] + b0.y, 0.f),
                                    fmaxf(acc[i][2] + b0.z, 0.f),
                                    fmaxf(acc[i][3] + b0.w, 0.f));
            float4 s1 = make_float4(fmaxf(acc[i][4] + b1.x, 0.f),
                                    fmaxf(acc[i][5] + b1.y, 0.f),
                                    fmaxf(acc[i][6] + b1.z, 0.f),
                                    fmaxf(acc[i][7] + b1.w, 0.f));
            *(float4*)&out[(size_t)r * 128 + c0]     = s0;
            *(float4*)&out[(size_t)r * 128 + c0 + 4] = s1;
        }
    }
}

// ---------------- final 128->32 GEMM + softmax (warp per row) ----------------
__global__ void __launch_bounds__(256)
mlp2_softmax_kernel(const float* __restrict__ tin, const float* __restrict__ Wm2,
                    const float* __restrict__ bm2, float* __restrict__ out) {
    __shared__ float Ws[D * P];
    __shared__ float bs[P];
    for (int i = threadIdx.x; i < D * P; i += blockDim.x) Ws[i] = Wm2[i];
    if (threadIdx.x < P) bs[threadIdx.x] = bm2[threadIdx.x];
    __syncthreads();

    int warp = threadIdx.x >> 5, lane = threadIdx.x & 31;
    int wpb = blockDim.x >> 5;
    for (int row = blockIdx.x * wpb + warp; row < NN; row += gridDim.x * wpb) {
        float4 a = __ldg(&((const float4*)tin)[(size_t)row * 32 + lane]);
        float av[4] = {a.x, a.y, a.z, a.w};
        float acc = bs[lane];
#pragma unroll
        for (int k = 0; k < 128; k++) {
            float xk = __shfl_sync(0xffffffffu, av[k & 3], k >> 2);
            acc = fmaf(xk, Ws[k * P + lane], acc);
        }
        float m = acc;
#pragma unroll
        for (int o = 16; o; o >>= 1) m = fmaxf(m, __shfl_xor_sync(0xffffffffu, m, o));
        float e = expf(acc - m);
        float s = e;
#pragma unroll
        for (int o = 16; o; o >>= 1) s += __shfl_xor_sync(0xffffffffu, s, o);
        out[(size_t)row * P + lane] = e / s;
    }
}

// ---------------- launch ------------------------------------------------------
extern "C" void kernel_launch(void* const* d_in, const int* in_sizes, int n_in,
                              void* d_out, int out_size) {
    const float* x   = (const float*)d_in[0];
    const int*   ni  = (const int*)  d_in[1];
    const int*   ei  = (const int*)  d_in[2];
    const float* W1  = (const float*)d_in[3];
    const float* b1  = (const float*)d_in[4];
    const float* W2  = (const float*)d_in[5];
    const float* b2  = (const float*)d_in[6];
    const float* Wm1 = (const float*)d_in[7];
    const float* bm1 = (const float*)d_in[8];
    const float* Wm2 = (const float*)d_in[9];
    const float* bm2 = (const float*)d_in[10];
    float* out = (float*)d_out;
    (void)in_sizes; (void)n_in; (void)out_size;

    cudaFuncSetAttribute(gemm128_relu_kernel,
                         cudaFuncAttributeMaxDynamicSharedMemorySize,
                         GEMM_SMEM_BYTES);

    float* efeat; cudaGetSymbolAddress((void**)&efeat, g_efeat);
    float* agg;   cudaGetSymbolAddress((void**)&agg,   g_agg);
    float* h1;    cudaGetSymbolAddress((void**)&h1,    g_h1);
    float* h2;    cudaGetSymbolAddress((void**)&h2,    g_h2);
    float* tbuf;  cudaGetSymbolAddress((void**)&tbuf,  g_t);
    int* ecnt;  cudaGetSymbolAddress((void**)&ecnt,  g_ecnt);
    int* ncnt;  cudaGetSymbolAddress((void**)&ncnt,  g_ncnt);
    int* eoff;  cudaGetSymbolAddress((void**)&eoff,  g_eoff);
    int* noff;  cudaGetSymbolAddress((void**)&noff,  g_noff);
    int* ecur;  cudaGetSymbolAddress((void**)&ecur,  g_ecur);
    int* ncur;  cudaGetSymbolAddress((void**)&ncur,  g_ncur);
    int* epins; cudaGetSymbolAddress((void**)&epins, g_epins);
    int* npins; cudaGetSymbolAddress((void**)&npins, g_npins);
    int* esums; cudaGetSymbolAddress((void**)&esums, g_esums);
    int* nsums; cudaGetSymbolAddress((void**)&nsums, g_nsums);

    // ---- CSR build (per call; deterministic) ----
    zero_counts_kernel<<<512, 256>>>();
    count_kernel<<<(NNZV + 255) / 256, 256>>>(ni, ei);
    scan_block_kernel<<<EBLK, 256>>>(ecnt, NE, eoff, esums);
    scan_block_kernel<<<NBLK, 256>>>(ncnt, NN, noff, nsums);
    scan_sums_kernel<<<2, 256>>>();
    scan_add_kernel<<<(NE + 255) / 256, 256>>>(eoff, ecur, esums, NE);
    scan_add_kernel<<<(NN + 255) / 256, 256>>>(noff, ncur, nsums, NN);
    fill_kernel<<<(NNZV + 255) / 256, 256>>>(ni, ei);

    const int egrid = (NE + 7) / 8;    // warp per edge
    const int ngrid = (NN + 7) / 8;    // warp per node

    // ---- hconv layer 1: x -> h1 ----
    seg_mean_gather_kernel<<<egrid, 256>>>(x, efeat, eoff, ecnt, epins, NE);
    seg_mean_gather_kernel<<<ngrid, 256>>>(efeat, agg, noff, ncnt, npins, NN);
    gemm128_relu_kernel<<<(NN + 127) / 128, 256, GEMM_SMEM_BYTES>>>(
        agg, W1, b1, h1, NN);

    // ---- hconv layer 2: h1 -> h2 ----
    seg_mean_gather_kernel<<<egrid, 256>>>(h1, efeat, eoff, ecnt, epins, NE);
    seg_mean_gather_kernel<<<ngrid, 256>>>(efeat, agg, noff, ncnt, npins, NN);
    gemm128_relu_kernel<<<(NN + 127) / 128, 256, GEMM_SMEM_BYTES>>>(
        agg, W2, b2, h2, NN);

    // ---- MLP hidden: h2 -> t ----
    gemm128_relu_kernel<<<(NN + 127) / 128, 256, GEMM_SMEM_BYTES>>>(
        h2, Wm1, bm1, tbuf, NN);

    // ---- logits + softmax -> out ----
    mlp2_softmax_kernel<<<2048, 256>>>(tbuf, Wm2, bm2, out);
}

// round 4
// speedup vs baseline: 2.0606x; 1.6256x over previous
#include <cuda_runtime.h>
#include <cstdint>

#define NN   100000   // nodes
#define NE   200000   // hyperedges
#define NNZV 800000   // pins
#define D    128
#define P    32

#define EBLK ((NE + 1023) / 1024)
#define NBLK ((NN + 1023) / 1024)

#define KPAD 132      // smem stride for transposed weights / t-tile
#define APAD 36       // smem stride for A chunks

// ---------------- scratch (device globals; no allocation allowed) -----------
__device__ float g_efeat[(size_t)NE * D];
__device__ float g_agg[(size_t)NN * D];
__device__ float g_h1[(size_t)NN * D];
__device__ float g_h2[(size_t)NN * D];
__device__ int   g_ecnt[NE];
__device__ int   g_ncnt[NN];
__device__ int   g_eoff[NE];
__device__ int   g_noff[NN];
__device__ int   g_ecur[NE];
__device__ int   g_ncur[NN];
__device__ int   g_epins[NNZV];
__device__ int   g_npins[NNZV];
__device__ int   g_esums[256];
__device__ int   g_nsums[256];

// ---------------- CSR build ---------------------------------------------------
__global__ void zero_counts_kernel() {
    int i = blockIdx.x * blockDim.x + threadIdx.x;
    int stride = gridDim.x * blockDim.x;
    for (int t = i; t < NE; t += stride) g_ecnt[t] = 0;
    for (int t = i; t < NN; t += stride) g_ncnt[t] = 0;
}

__global__ void count_kernel(const int* __restrict__ ni, const int* __restrict__ ei) {
    int t = blockIdx.x * blockDim.x + threadIdx.x;
    if (t < NNZV) {
        atomicAdd(&g_ecnt[ei[t]], 1);
        atomicAdd(&g_ncnt[ni[t]], 1);
    }
}

__global__ void __launch_bounds__(256)
scan_block_kernel(const int* __restrict__ cnt, int n,
                  int* __restrict__ out, int* __restrict__ sums) {
    __shared__ int sm[256];
    int tid = threadIdx.x;
    int base = blockIdx.x * 1024 + tid * 4;
    int v[4]; int s = 0;
#pragma unroll
    for (int i = 0; i < 4; i++) {
        int idx = base + i;
        v[i] = (idx < n) ? cnt[idx] : 0;
        s += v[i];
    }
    sm[tid] = s; __syncthreads();
    for (int off = 1; off < 256; off <<= 1) {
        int u = (tid >= off) ? sm[tid - off] : 0;
        __syncthreads();
        sm[tid] += u;
        __syncthreads();
    }
    int excl = sm[tid] - s;
    if (tid == 255) sums[blockIdx.x] = sm[255];
    int run = excl;
#pragma unroll
    for (int i = 0; i < 4; i++) {
        int idx = base + i;
        if (idx < n) out[idx] = run;
        run += v[i];
    }
}

__global__ void __launch_bounds__(256) scan_sums_kernel() {
    int* sums = (blockIdx.x == 0) ? g_esums : g_nsums;
    int nb    = (blockIdx.x == 0) ? EBLK : NBLK;
    __shared__ int sm[256];
    int tid = threadIdx.x;
    int s = (tid < nb) ? sums[tid] : 0;
    sm[tid] = s; __syncthreads();
    for (int off = 1; off < 256; off <<= 1) {
        int u = (tid >= off) ? sm[tid - off] : 0;
        __syncthreads();
        sm[tid] += u;
        __syncthreads();
    }
    sums[tid] = sm[tid];
}

__global__ void scan_add_kernel(int* __restrict__ offp, int* __restrict__ cur,
                                const int* __restrict__ sums, int n) {
    int idx = blockIdx.x * blockDim.x + threadIdx.x;
    if (idx < n) {
        int b = idx >> 10;
        int add = (b > 0) ? sums[b - 1] : 0;
        int v = offp[idx] + add;
        offp[idx] = v;
        cur[idx] = v;
    }
}

__global__ void fill_kernel(const int* __restrict__ ni, const int* __restrict__ ei) {
    int t = blockIdx.x * blockDim.x + threadIdx.x;
    if (t < NNZV) {
        int n = ni[t], e = ei[t];
        g_epins[atomicAdd(&g_ecur[e], 1)] = n;
        g_npins[atomicAdd(&g_ncur[n], 1)] = e;
    }
}

// ---------------- segment-mean gather (warp per segment) ---------------------
__global__ void __launch_bounds__(256)
seg_mean_gather_kernel(const float* __restrict__ src, float* __restrict__ dst,
                       const int* __restrict__ offs, const int* __restrict__ cnts,
                       const int* __restrict__ pins, int nseg) {
    int w = blockIdx.x * 8 + (threadIdx.x >> 5);
    if (w >= nseg) return;
    int lane = threadIdx.x & 31;
    int off = __ldg(&offs[w]);
    int deg = __ldg(&cnts[w]);
    const float4* s4 = (const float4*)src;
    float4 acc = make_float4(0.f, 0.f, 0.f, 0.f);
    for (int j = 0; j < deg; j += 32) {
        int rem = deg - j;
        int idx = (lane < rem) ? __ldg(&pins[off + j + lane]) : 0;
        int kmax = rem < 32 ? rem : 32;
        for (int k = 0; k < kmax; k++) {
            int r = __shfl_sync(0xffffffffu, idx, k);
            float4 v = __ldg(&s4[(size_t)r * 32 + lane]);
            acc.x += v.x; acc.y += v.y; acc.z += v.z; acc.w += v.w;
        }
    }
    float sc = 1.0f / (float)(deg > 0 ? deg : 1);
    acc.x *= sc; acc.y *= sc; acc.z *= sc; acc.w *= sc;
    ((float4*)dst)[(size_t)w * 32 + lane] = acc;
}

// ---------------- tf32 mma helpers -------------------------------------------
__device__ __forceinline__ uint32_t f2tf(float v) {
    uint32_t t;
    asm("cvt.rna.tf32.f32 %0, %1;" : "=r"(t) : "f"(v));
    return t;
}

__device__ __forceinline__ void mma_tf32(float* c,
                                         uint32_t a0, uint32_t a1, uint32_t a2, uint32_t a3,
                                         uint32_t b0, uint32_t b1) {
    asm volatile("mma.sync.aligned.m16n8k8.row.col.f32.tf32.tf32.f32 "
                 "{%0,%1,%2,%3}, {%4,%5,%6,%7}, {%8,%9}, {%0,%1,%2,%3};"
                 : "+f"(c[0]), "+f"(c[1]), "+f"(c[2]), "+f"(c[3])
                 : "r"(a0), "r"(a1), "r"(a2), "r"(a3), "r"(b0), "r"(b1));
}

#define GEMM_SMEM_BYTES ((128 * KPAD + 128 * APAD) * 4)

// Shared mainloop: acc[16][4] = in_tile(128x128) @ W (tf32). WsT/As in smem.
// WsT must be pre-filled ([n][KPAD], tf32 bits). Returns with acc populated.
__device__ __forceinline__ void gemm_mainloop(const float* __restrict__ in, int nrows,
                                              uint32_t* WsT, uint32_t* As,
                                              int row0, int warp, int lane,
                                              float acc[16][4]) {
    const int tid = threadIdx.x;
    const int wr = warp * 16;
    const int q = lane >> 2, p = lane & 3;
#pragma unroll
    for (int nf = 0; nf < 16; nf++)
#pragma unroll
        for (int j = 0; j < 4; j++) acc[nf][j] = 0.f;

    for (int kc = 0; kc < 4; kc++) {
        __syncthreads();
        for (int i = tid; i < 128 * 32; i += 256) {
            int r = i >> 5, kk = i & 31;
            int gr = row0 + r;
            float v = (gr < nrows) ? __ldg(&in[(size_t)gr * 128 + kc * 32 + kk]) : 0.f;
            As[r * APAD + kk] = f2tf(v);
        }
        __syncthreads();
#pragma unroll
        for (int ks = 0; ks < 4; ks++) {
            int k0 = ks * 8;
            uint32_t a0 = As[(wr + q) * APAD + k0 + p];
            uint32_t a1 = As[(wr + q + 8) * APAD + k0 + p];
            uint32_t a2 = As[(wr + q) * APAD + k0 + p + 4];
            uint32_t a3 = As[(wr + q + 8) * APAD + k0 + p + 4];
            int kg = kc * 32 + k0;
#pragma unroll
            for (int nf = 0; nf < 16; nf++) {
                uint32_t b0 = WsT[(nf * 8 + q) * KPAD + kg + p];
                uint32_t b1 = WsT[(nf * 8 + q) * KPAD + kg + p + 4];
                mma_tf32(acc[nf], a0, a1, a2, a3, b0, b1);
            }
        }
    }
}

// ---------------- GEMM(128x128) + bias + ReLU (tf32) -------------------------
__global__ void __launch_bounds__(256)
gemm_tf32_relu_kernel(const float* __restrict__ in, const float* __restrict__ W,
                      const float* __restrict__ b, float* __restrict__ out, int nrows) {
    extern __shared__ float smf[];
    uint32_t* WsT = (uint32_t*)smf;              // [128][KPAD]
    uint32_t* As  = (uint32_t*)(smf + 128 * KPAD); // [128][APAD]
    const int tid = threadIdx.x;

    for (int i = tid; i < 128 * 128; i += 256) {
        int k = i >> 7, n = i & 127;
        WsT[n * KPAD + k] = f2tf(__ldg(&W[i]));
    }
    int row0 = blockIdx.x * 128;
    int warp = tid >> 5, lane = tid & 31;
    float acc[16][4];
    gemm_mainloop(in, nrows, WsT, As, row0, warp, lane, acc);

    const int q = lane >> 2, p = lane & 3;
    int r_lo = row0 + warp * 16 + q;
    int r_hi = r_lo + 8;
#pragma unroll
    for (int nf = 0; nf < 16; nf++) {
        int c = nf * 8 + 2 * p;
        float bx = __ldg(&b[c]), by = __ldg(&b[c + 1]);
        if (r_lo < nrows) {
            float2 v = make_float2(fmaxf(acc[nf][0] + bx, 0.f),
                                   fmaxf(acc[nf][1] + by, 0.f));
            *(float2*)&out[(size_t)r_lo * 128 + c] = v;
        }
        if (r_hi < nrows) {
            float2 v = make_float2(fmaxf(acc[nf][2] + bx, 0.f),
                                   fmaxf(acc[nf][3] + by, 0.f));
            *(float2*)&out[(size_t)r_hi * 128 + c] = v;
        }
    }
}

// ---------------- fused: relu(in@Wm1+bm1) @ Wm2 + bm2, softmax ---------------
__global__ void __launch_bounds__(256)
fused_mlp_softmax_kernel(const float* __restrict__ in,
                         const float* __restrict__ Wm1, const float* __restrict__ bm1,
                         const float* __restrict__ Wm2, const float* __restrict__ bm2,
                         float* __restrict__ out, int nrows) {
    extern __shared__ float smf[];
    uint32_t* WsT = (uint32_t*)smf;                // [128][KPAD]; later t-tile
    uint32_t* As  = (uint32_t*)(smf + 128 * KPAD); // [128][APAD]; later Wm2T
    __shared__ float bs2[P];
    const int tid = threadIdx.x;

    for (int i = tid; i < 128 * 128; i += 256) {
        int k = i >> 7, n = i & 127;
        WsT[n * KPAD + k] = f2tf(__ldg(&Wm1[i]));
    }
    if (tid < P) bs2[tid] = bm2[tid];

    int row0 = blockIdx.x * 128;
    int warp = tid >> 5, lane = tid & 31;
    const int wr = warp * 16;
    const int q = lane >> 2, p = lane & 3;
    float acc[16][4];
    gemm_mainloop(in, nrows, WsT, As, row0, warp, lane, acc);

    // phase 2: t-tile (tf32) into WsT region; Wm2 transposed into As region
    __syncthreads();   // everyone done reading WsT/As
    uint32_t* Ts    = WsT;  // [128 rows][KPAD]
    uint32_t* W2sT  = As;   // [32 n][KPAD]  (32*132 = 4224 <= 128*36)
#pragma unroll
    for (int nf = 0; nf < 16; nf++) {
        int c = nf * 8 + 2 * p;
        float bx = __ldg(&bm1[c]), by = __ldg(&bm1[c + 1]);
        Ts[(wr + q) * KPAD + c]         = f2tf(fmaxf(acc[nf][0] + bx, 0.f));
        Ts[(wr + q) * KPAD + c + 1]     = f2tf(fmaxf(acc[nf][1] + by, 0.f));
        Ts[(wr + q + 8) * KPAD + c]     = f2tf(fmaxf(acc[nf][2] + bx, 0.f));
        Ts[(wr + q + 8) * KPAD + c + 1] = f2tf(fmaxf(acc[nf][3] + by, 0.f));
    }
    for (int i = tid; i < 128 * 32; i += 256) {
        int k = i >> 5, n = i & 31;
        W2sT[n * KPAD + k] = f2tf(__ldg(&Wm2[i]));
    }
    __syncthreads();

    // phase 3: logits(16 rows x 32 cols per warp) = t @ Wm2
    float acc2[4][4];
#pragma unroll
    for (int nf = 0; nf < 4; nf++)
#pragma unroll
        for (int j = 0; j < 4; j++) acc2[nf][j] = 0.f;
#pragma unroll
    for (int ks = 0; ks < 16; ks++) {
        int k0 = ks * 8;
        uint32_t a0 = Ts[(wr + q) * KPAD + k0 + p];
        uint32_t a1 = Ts[(wr + q + 8) * KPAD + k0 + p];
        uint32_t a2 = Ts[(wr + q) * KPAD + k0 + p + 4];
        uint32_t a3 = Ts[(wr + q + 8) * KPAD + k0 + p + 4];
#pragma unroll
        for (int nf = 0; nf < 4; nf++) {
            uint32_t b0 = W2sT[(nf * 8 + q) * KPAD + k0 + p];
            uint32_t b1 = W2sT[(nf * 8 + q) * KPAD + k0 + p + 4];
            mma_tf32(acc2[nf], a0, a1, a2, a3, b0, b1);
        }
    }

    // phase 4: softmax over 32 cols, two rows per thread
    float vlo[8], vhi[8];
#pragma unroll
    for (int nf = 0; nf < 4; nf++) {
        int c = nf * 8 + 2 * p;
        vlo[nf * 2]     = acc2[nf][0] + bs2[c];
        vlo[nf * 2 + 1] = acc2[nf][1] + bs2[c + 1];
        vhi[nf * 2]     = acc2[nf][2] + bs2[c];
        vhi[nf * 2 + 1] = acc2[nf][3] + bs2[c + 1];
    }
    float mlo = vlo[0], mhi = vhi[0];
#pragma unroll
    for (int j = 1; j < 8; j++) { mlo = fmaxf(mlo, vlo[j]); mhi = fmaxf(mhi, vhi[j]); }
    mlo = fmaxf(mlo, __shfl_xor_sync(0xffffffffu, mlo, 1));
    mlo = fmaxf(mlo, __shfl_xor_sync(0xffffffffu, mlo, 2));
    mhi = fmaxf(mhi, __shfl_xor_sync(0xffffffffu, mhi, 1));
    mhi = fmaxf(mhi, __shfl_xor_sync(0xffffffffu, mhi, 2));
    float slo = 0.f, shi = 0.f;
#pragma unroll
    for (int j = 0; j < 8; j++) {
        vlo[j] = __expf(vlo[j] - mlo); slo += vlo[j];
        vhi[j] = __expf(vhi[j] - mhi); shi += vhi[j];
    }
    slo += __shfl_xor_sync(0xffffffffu, slo, 1);
    slo += __shfl_xor_sync(0xffffffffu, slo, 2);
    shi += __shfl_xor_sync(0xffffffffu, shi, 1);
    shi += __shfl_xor_sync(0xffffffffu, shi, 2);
    float rlo = 1.f / slo, rhi = 1.f / shi;

    int r_lo = row0 + wr + q;
    int r_hi = r_lo + 8;
#pragma unroll
    for (int nf = 0; nf < 4; nf++) {
        int c = nf * 8 + 2 * p;
        if (r_lo < nrows)
            *(float2*)&out[(size_t)r_lo * P + c] =
                make_float2(vlo[nf * 2] * rlo, vlo[nf * 2 + 1] * rlo);
        if (r_hi < nrows)
            *(float2*)&out[(size_t)r_hi * P + c] =
                make_float2(vhi[nf * 2] * rhi, vhi[nf * 2 + 1] * rhi);
    }
}

// ---------------- launch ------------------------------------------------------
extern "C" void kernel_launch(void* const* d_in, const int* in_sizes, int n_in,
                              void* d_out, int out_size) {
    const float* x   = (const float*)d_in[0];
    const int*   ni  = (const int*)  d_in[1];
    const int*   ei  = (const int*)  d_in[2];
    const float* W1  = (const float*)d_in[3];
    const float* b1  = (const float*)d_in[4];
    const float* W2  = (const float*)d_in[5];
    const float* b2  = (const float*)d_in[6];
    const float* Wm1 = (const float*)d_in[7];
    const float* bm1 = (const float*)d_in[8];
    const float* Wm2 = (const float*)d_in[9];
    const float* bm2 = (const float*)d_in[10];
    float* out = (float*)d_out;
    (void)in_sizes; (void)n_in; (void)out_size;

    cudaFuncSetAttribute(gemm_tf32_relu_kernel,
                         cudaFuncAttributeMaxDynamicSharedMemorySize, GEMM_SMEM_BYTES);
    cudaFuncSetAttribute(fused_mlp_softmax_kernel,
                         cudaFuncAttributeMaxDynamicSharedMemorySize, GEMM_SMEM_BYTES);

    float* efeat; cudaGetSymbolAddress((void**)&efeat, g_efeat);
    float* agg;   cudaGetSymbolAddress((void**)&agg,   g_agg);
    float* h1;    cudaGetSymbolAddress((void**)&h1,    g_h1);
    float* h2;    cudaGetSymbolAddress((void**)&h2,    g_h2);
    int* ecnt;  cudaGetSymbolAddress((void**)&ecnt,  g_ecnt);
    int* ncnt;  cudaGetSymbolAddress((void**)&ncnt,  g_ncnt);
    int* eoff;  cudaGetSymbolAddress((void**)&eoff,  g_eoff);
    int* noff;  cudaGetSymbolAddress((void**)&noff,  g_noff);
    int* ecur;  cudaGetSymbolAddress((void**)&ecur,  g_ecur);
    int* ncur;  cudaGetSymbolAddress((void**)&ncur,  g_ncur);
    int* epins; cudaGetSymbolAddress((void**)&epins, g_epins);
    int* npins; cudaGetSymbolAddress((void**)&npins, g_npins);
    int* esums; cudaGetSymbolAddress((void**)&esums, g_esums);
    int* nsums; cudaGetSymbolAddress((void**)&nsums, g_nsums);

    // ---- CSR build ----
    zero_counts_kernel<<<512, 256>>>();
    count_kernel<<<(NNZV + 255) / 256, 256>>>(ni, ei);
    scan_block_kernel<<<EBLK, 256>>>(ecnt, NE, eoff, esums);
    scan_block_kernel<<<NBLK, 256>>>(ncnt, NN, noff, nsums);
    scan_sums_kernel<<<2, 256>>>();
    scan_add_kernel<<<(NE + 255) / 256, 256>>>(eoff, ecur, esums, NE);
    scan_add_kernel<<<(NN + 255) / 256, 256>>>(noff, ncur, nsums, NN);
    fill_kernel<<<(NNZV + 255) / 256, 256>>>(ni, ei);

    const int egrid = (NE + 7) / 8;
    const int ngrid = (NN + 7) / 8;
    const int ggrid = (NN + 127) / 128;

    // ---- hconv layer 1 ----
    seg_mean_gather_kernel<<<egrid, 256>>>(x, efeat, eoff, ecnt, epins, NE);
    seg_mean_gather_kernel<<<ngrid, 256>>>(efeat, agg, noff, ncnt, npins, NN);
    gemm_tf32_relu_kernel<<<ggrid, 256, GEMM_SMEM_BYTES>>>(agg, W1, b1, h1, NN);

    // ---- hconv layer 2 ----
    seg_mean_gather_kernel<<<egrid, 256>>>(h1, efeat, eoff, ecnt, epins, NE);
    seg_mean_gather_kernel<<<ngrid, 256>>>(efeat, agg, noff, ncnt, npins, NN);
    gemm_tf32_relu_kernel<<<ggrid, 256, GEMM_SMEM_BYTES>>>(agg, W2, b2, h2, NN);

    // ---- fused MLP + softmax ----
    fused_mlp_softmax_kernel<<<ggrid, 256, GEMM_SMEM_BYTES>>>(
        h2, Wm1, bm1, Wm2, bm2, out, NN);
}

// round 5
// speedup vs baseline: 2.5853x; 1.2546x over previous
#include <cuda_runtime.h>
#include <cuda_bf16.h>
#include <cstdint>

#define NN   100000   // nodes
#define NE   200000   // hyperedges
#define NNZV 800000   // pins
#define D    128
#define P    32

#define EBLK ((NE + 1023) / 1024)
#define NBLK ((NN + 1023) / 1024)

#define KPAD 132      // smem stride for transposed weights / t-tile
#define APAD 36       // smem stride for A chunks

// ---------------- scratch (device globals; no allocation allowed) -----------
__device__ __nv_bfloat16 g_xb[(size_t)NN * D];     // x converted (25.6 MB)
__device__ __nv_bfloat16 g_efeat[(size_t)NE * D];  // edge means (51.2 MB)
__device__ __nv_bfloat16 g_agg[(size_t)NN * D];    // node means (25.6 MB)
__device__ __nv_bfloat16 g_h1[(size_t)NN * D];
__device__ __nv_bfloat16 g_h2[(size_t)NN * D];
__device__ int   g_ecnt[NE];
__device__ int   g_ncnt[NN];
__device__ int   g_eoff[NE];
__device__ int   g_noff[NN];
__device__ int   g_ecur[NE];
__device__ int   g_ncur[NN];
__device__ int   g_epins[NNZV];
__device__ int   g_npins[NNZV];
__device__ int   g_esums[256];
__device__ int   g_nsums[256];

// ---------------- CSR build ---------------------------------------------------
__global__ void zero_counts_kernel() {
    int i = blockIdx.x * blockDim.x + threadIdx.x;
    int stride = gridDim.x * blockDim.x;
    for (int t = i; t < NE; t += stride) g_ecnt[t] = 0;
    for (int t = i; t < NN; t += stride) g_ncnt[t] = 0;
}

__global__ void count_kernel(const int* __restrict__ ni, const int* __restrict__ ei) {
    int t = blockIdx.x * blockDim.x + threadIdx.x;
    if (t < NNZV) {
        atomicAdd(&g_ecnt[ei[t]], 1);
        atomicAdd(&g_ncnt[ni[t]], 1);
    }
}

__global__ void __launch_bounds__(256)
scan_block_kernel(const int* __restrict__ cnt, int n,
                  int* __restrict__ out, int* __restrict__ sums) {
    __shared__ int sm[256];
    int tid = threadIdx.x;
    int base = blockIdx.x * 1024 + tid * 4;
    int v[4]; int s = 0;
#pragma unroll
    for (int i = 0; i < 4; i++) {
        int idx = base + i;
        v[i] = (idx < n) ? cnt[idx] : 0;
        s += v[i];
    }
    sm[tid] = s; __syncthreads();
    for (int off = 1; off < 256; off <<= 1) {
        int u = (tid >= off) ? sm[tid - off] : 0;
        __syncthreads();
        sm[tid] += u;
        __syncthreads();
    }
    int excl = sm[tid] - s;
    if (tid == 255) sums[blockIdx.x] = sm[255];
    int run = excl;
#pragma unroll
    for (int i = 0; i < 4; i++) {
        int idx = base + i;
        if (idx < n) out[idx] = run;
        run += v[i];
    }
}

__global__ void __launch_bounds__(256) scan_sums_kernel() {
    int* sums = (blockIdx.x == 0) ? g_esums : g_nsums;
    int nb    = (blockIdx.x == 0) ? EBLK : NBLK;
    __shared__ int sm[256];
    int tid = threadIdx.x;
    int s = (tid < nb) ? sums[tid] : 0;
    sm[tid] = s; __syncthreads();
    for (int off = 1; off < 256; off <<= 1) {
        int u = (tid >= off) ? sm[tid - off] : 0;
        __syncthreads();
        sm[tid] += u;
        __syncthreads();
    }
    sums[tid] = sm[tid];
}

__global__ void scan_add_kernel(int* __restrict__ offp, int* __restrict__ cur,
                                const int* __restrict__ sums, int n) {
    int idx = blockIdx.x * blockDim.x + threadIdx.x;
    if (idx < n) {
        int b = idx >> 10;
        int add = (b > 0) ? sums[b - 1] : 0;
        int v = offp[idx] + add;
        offp[idx] = v;
        cur[idx] = v;
    }
}

__global__ void fill_kernel(const int* __restrict__ ni, const int* __restrict__ ei) {
    int t = blockIdx.x * blockDim.x + threadIdx.x;
    if (t < NNZV) {
        int n = ni[t], e = ei[t];
        g_epins[atomicAdd(&g_ecur[e], 1)] = n;
        g_npins[atomicAdd(&g_ncur[n], 1)] = e;
    }
}

// ---------------- fp32 -> bf16 convert ---------------------------------------
__global__ void __launch_bounds__(256)
f2bf_kernel(const float* __restrict__ src, __nv_bfloat16* __restrict__ dst, int n4) {
    int i = blockIdx.x * blockDim.x + threadIdx.x;
    int stride = gridDim.x * blockDim.x;
    const float4* s4 = (const float4*)src;
    uint2* d2 = (uint2*)dst;
    for (int t = i; t < n4; t += stride) {
        float4 v = __ldg(&s4[t]);
        __nv_bfloat162 lo = __float22bfloat162_rn(make_float2(v.x, v.y));
        __nv_bfloat162 hi = __float22bfloat162_rn(make_float2(v.z, v.w));
        uint2 o;
        o.x = *(uint32_t*)&lo;
        o.y = *(uint32_t*)&hi;
        d2[t] = o;
    }
}

// ---------------- segment-mean gather (warp per segment, bf16) ---------------
// Row = 128 bf16 = 256B; lane handles 8B (4 bf16). fp32 accumulation.
__global__ void __launch_bounds__(256)
seg_mean_gather_kernel(const __nv_bfloat16* __restrict__ src,
                       __nv_bfloat16* __restrict__ dst,
                       const int* __restrict__ offs, const int* __restrict__ cnts,
                       const int* __restrict__ pins, int nseg) {
    int w = blockIdx.x * 8 + (threadIdx.x >> 5);
    if (w >= nseg) return;
    int lane = threadIdx.x & 31;
    int off = __ldg(&offs[w]);
    int deg = __ldg(&cnts[w]);
    const uint2* s2 = (const uint2*)src;
    float4 acc = make_float4(0.f, 0.f, 0.f, 0.f);
    for (int j = 0; j < deg; j += 32) {
        int rem = deg - j;
        int idx = (lane < rem) ? __ldg(&pins[off + j + lane]) : 0;
        int kmax = rem < 32 ? rem : 32;
        for (int k = 0; k < kmax; k++) {
            int r = __shfl_sync(0xffffffffu, idx, k);
            uint2 v = __ldg(&s2[(size_t)r * 32 + lane]);
            float2 lo = __bfloat1622float2(*(__nv_bfloat162*)&v.x);
            float2 hi = __bfloat1622float2(*(__nv_bfloat162*)&v.y);
            acc.x += lo.x; acc.y += lo.y; acc.z += hi.x; acc.w += hi.y;
        }
    }
    float sc = 1.0f / (float)(deg > 0 ? deg : 1);
    __nv_bfloat162 olo = __float22bfloat162_rn(make_float2(acc.x * sc, acc.y * sc));
    __nv_bfloat162 ohi = __float22bfloat162_rn(make_float2(acc.z * sc, acc.w * sc));
    uint2 o;
    o.x = *(uint32_t*)&olo;
    o.y = *(uint32_t*)&ohi;
    ((uint2*)dst)[(size_t)w * 32 + lane] = o;
}

// ---------------- tf32 mma helpers -------------------------------------------
__device__ __forceinline__ uint32_t f2tf(float v) {
    uint32_t t;
    asm("cvt.rna.tf32.f32 %0, %1;" : "=r"(t) : "f"(v));
    return t;
}

__device__ __forceinline__ void mma_tf32(float* c,
                                         uint32_t a0, uint32_t a1, uint32_t a2, uint32_t a3,
                                         uint32_t b0, uint32_t b1) {
    asm volatile("mma.sync.aligned.m16n8k8.row.col.f32.tf32.tf32.f32 "
                 "{%0,%1,%2,%3}, {%4,%5,%6,%7}, {%8,%9}, {%0,%1,%2,%3};"
                 : "+f"(c[0]), "+f"(c[1]), "+f"(c[2]), "+f"(c[3])
                 : "r"(a0), "r"(a1), "r"(a2), "r"(a3), "r"(b0), "r"(b1));
}

#define GEMM_SMEM_BYTES ((128 * KPAD + 128 * APAD) * 4)

// Shared mainloop: acc[16][4] = in_tile(128x128 bf16) @ W (tf32 in WsT).
// bf16 bits << 16 are valid tf32 operands (mantissa subset).
__device__ __forceinline__ void gemm_mainloop(const __nv_bfloat16* __restrict__ in,
                                              int nrows,
                                              uint32_t* WsT, uint32_t* As,
                                              int row0, int warp, int lane,
                                              float acc[16][4]) {
    const int tid = threadIdx.x;
    const int wr = warp * 16;
    const int q = lane >> 2, p = lane & 3;
#pragma unroll
    for (int nf = 0; nf < 16; nf++)
#pragma unroll
        for (int j = 0; j < 4; j++) acc[nf][j] = 0.f;

    for (int kc = 0; kc < 4; kc++) {
        __syncthreads();
        // 128 rows x 32 cols chunk = 128*16 bf162 loads
        for (int i = tid; i < 128 * 16; i += 256) {
            int r = i >> 4, c2 = i & 15;
            int gr = row0 + r;
            uint32_t v = 0;
            if (gr < nrows)
                v = __ldg((const uint32_t*)&in[(size_t)gr * 128 + kc * 32 + c2 * 2]);
            As[r * APAD + c2 * 2]     = (v & 0xffffu) << 16;
            As[r * APAD + c2 * 2 + 1] = v & 0xffff0000u;
        }
        __syncthreads();
#pragma unroll
        for (int ks = 0; ks < 4; ks++) {
            int k0 = ks * 8;
            uint32_t a0 = As[(wr + q) * APAD + k0 + p];
            uint32_t a1 = As[(wr + q + 8) * APAD + k0 + p];
            uint32_t a2 = As[(wr + q) * APAD + k0 + p + 4];
            uint32_t a3 = As[(wr + q + 8) * APAD + k0 + p + 4];
            int kg = kc * 32 + k0;
#pragma unroll
            for (int nf = 0; nf < 16; nf++) {
                uint32_t b0 = WsT[(nf * 8 + q) * KPAD + kg + p];
                uint32_t b1 = WsT[(nf * 8 + q) * KPAD + kg + p + 4];
                mma_tf32(acc[nf], a0, a1, a2, a3, b0, b1);
            }
        }
    }
}

// ---------------- GEMM(128x128) + bias + ReLU -> bf16 ------------------------
__global__ void __launch_bounds__(256)
gemm_tf32_relu_kernel(const __nv_bfloat16* __restrict__ in,
                      const float* __restrict__ W, const float* __restrict__ b,
                      __nv_bfloat16* __restrict__ out, int nrows) {
    extern __shared__ float smf[];
    uint32_t* WsT = (uint32_t*)smf;                // [128][KPAD]
    uint32_t* As  = (uint32_t*)(smf + 128 * KPAD); // [128][APAD]
    const int tid = threadIdx.x;

    for (int i = tid; i < 128 * 128; i += 256) {
        int k = i >> 7, n = i & 127;
        WsT[n * KPAD + k] = f2tf(__ldg(&W[i]));
    }
    int row0 = blockIdx.x * 128;
    int warp = tid >> 5, lane = tid & 31;
    float acc[16][4];
    gemm_mainloop(in, nrows, WsT, As, row0, warp, lane, acc);

    const int q = lane >> 2, p = lane & 3;
    int r_lo = row0 + warp * 16 + q;
    int r_hi = r_lo + 8;
#pragma unroll
    for (int nf = 0; nf < 16; nf++) {
        int c = nf * 8 + 2 * p;
        float bx = __ldg(&b[c]), by = __ldg(&b[c + 1]);
        if (r_lo < nrows) {
            __nv_bfloat162 v = __float22bfloat162_rn(
                make_float2(fmaxf(acc[nf][0] + bx, 0.f), fmaxf(acc[nf][1] + by, 0.f)));
            *(uint32_t*)&out[(size_t)r_lo * 128 + c] = *(uint32_t*)&v;
        }
        if (r_hi < nrows) {
            __nv_bfloat162 v = __float22bfloat162_rn(
                make_float2(fmaxf(acc[nf][2] + bx, 0.f), fmaxf(acc[nf][3] + by, 0.f)));
            *(uint32_t*)&out[(size_t)r_hi * 128 + c] = *(uint32_t*)&v;
        }
    }
}

// ---------------- fused: relu(in@Wm1+bm1) @ Wm2 + bm2, softmax ---------------
__global__ void __launch_bounds__(256)
fused_mlp_softmax_kernel(const __nv_bfloat16* __restrict__ in,
                         const float* __restrict__ Wm1, const float* __restrict__ bm1,
                         const float* __restrict__ Wm2, const float* __restrict__ bm2,
                         float* __restrict__ out, int nrows) {
    extern __shared__ float smf[];
    uint32_t* WsT = (uint32_t*)smf;                // [128][KPAD]; later t-tile
    uint32_t* As  = (uint32_t*)(smf + 128 * KPAD); // [128][APAD]; later Wm2T
    __shared__ float bs2[P];
    const int tid = threadIdx.x;

    for (int i = tid; i < 128 * 128; i += 256) {
        int k = i >> 7, n = i & 127;
        WsT[n * KPAD + k] = f2tf(__ldg(&Wm1[i]));
    }
    if (tid < P) bs2[tid] = bm2[tid];

    int row0 = blockIdx.x * 128;
    int warp = tid >> 5, lane = tid & 31;
    const int wr = warp * 16;
    const int q = lane >> 2, p = lane & 3;
    float acc[16][4];
    gemm_mainloop(in, nrows, WsT, As, row0, warp, lane, acc);

    __syncthreads();
    uint32_t* Ts   = WsT;  // [128 rows][KPAD]
    uint32_t* W2sT = As;   // [32 n][KPAD]
#pragma unroll
    for (int nf = 0; nf < 16; nf++) {
        int c = nf * 8 + 2 * p;
        float bx = __ldg(&bm1[c]), by = __ldg(&bm1[c + 1]);
        Ts[(wr + q) * KPAD + c]         = f2tf(fmaxf(acc[nf][0] + bx, 0.f));
        Ts[(wr + q) * KPAD + c + 1]     = f2tf(fmaxf(acc[nf][1] + by, 0.f));
        Ts[(wr + q + 8) * KPAD + c]     = f2tf(fmaxf(acc[nf][2] + bx, 0.f));
        Ts[(wr + q + 8) * KPAD + c + 1] = f2tf(fmaxf(acc[nf][3] + by, 0.f));
    }
    for (int i = tid; i < 128 * 32; i += 256) {
        int k = i >> 5, n = i & 31;
        W2sT[n * KPAD + k] = f2tf(__ldg(&Wm2[i]));
    }
    __syncthreads();

    float acc2[4][4];
#pragma unroll
    for (int nf = 0; nf < 4; nf++)
#pragma unroll
        for (int j = 0; j < 4; j++) acc2[nf][j] = 0.f;
#pragma unroll
    for (int ks = 0; ks < 16; ks++) {
        int k0 = ks * 8;
        uint32_t a0 = Ts[(wr + q) * KPAD + k0 + p];
        uint32_t a1 = Ts[(wr + q + 8) * KPAD + k0 + p];
        uint32_t a2 = Ts[(wr + q) * KPAD + k0 + p + 4];
        uint32_t a3 = Ts[(wr + q + 8) * KPAD + k0 + p + 4];
#pragma unroll
        for (int nf = 0; nf < 4; nf++) {
            uint32_t b0 = W2sT[(nf * 8 + q) * KPAD + k0 + p];
            uint32_t b1 = W2sT[(nf * 8 + q) * KPAD + k0 + p + 4];
            mma_tf32(acc2[nf], a0, a1, a2, a3, b0, b1);
        }
    }

    float vlo[8], vhi[8];
#pragma unroll
    for (int nf = 0; nf < 4; nf++) {
        int c = nf * 8 + 2 * p;
        vlo[nf * 2]     = acc2[nf][0] + bs2[c];
        vlo[nf * 2 + 1] = acc2[nf][1] + bs2[c + 1];
        vhi[nf * 2]     = acc2[nf][2] + bs2[c];
        vhi[nf * 2 + 1] = acc2[nf][3] + bs2[c + 1];
    }
    float mlo = vlo[0], mhi = vhi[0];
#pragma unroll
    for (int j = 1; j < 8; j++) { mlo = fmaxf(mlo, vlo[j]); mhi = fmaxf(mhi, vhi[j]); }
    mlo = fmaxf(mlo, __shfl_xor_sync(0xffffffffu, mlo, 1));
    mlo = fmaxf(mlo, __shfl_xor_sync(0xffffffffu, mlo, 2));
    mhi = fmaxf(mhi, __shfl_xor_sync(0xffffffffu, mhi, 1));
    mhi = fmaxf(mhi, __shfl_xor_sync(0xffffffffu, mhi, 2));
    float slo = 0.f, shi = 0.f;
#pragma unroll
    for (int j = 0; j < 8; j++) {
        vlo[j] = __expf(vlo[j] - mlo); slo += vlo[j];
        vhi[j] = __expf(vhi[j] - mhi); shi += vhi[j];
    }
    slo += __shfl_xor_sync(0xffffffffu, slo, 1);
    slo += __shfl_xor_sync(0xffffffffu, slo, 2);
    shi += __shfl_xor_sync(0xffffffffu, shi, 1);
    shi += __shfl_xor_sync(0xffffffffu, shi, 2);
    float rlo = 1.f / slo, rhi = 1.f / shi;

    int r_lo = row0 + wr + q;
    int r_hi = r_lo + 8;
#pragma unroll
    for (int nf = 0; nf < 4; nf++) {
        int c = nf * 8 + 2 * p;
        if (r_lo < nrows)
            *(float2*)&out[(size_t)r_lo * P + c] =
                make_float2(vlo[nf * 2] * rlo, vlo[nf * 2 + 1] * rlo);
        if (r_hi < nrows)
            *(float2*)&out[(size_t)r_hi * P + c] =
                make_float2(vhi[nf * 2] * rhi, vhi[nf * 2 + 1] * rhi);
    }
}

// ---------------- launch ------------------------------------------------------
extern "C" void kernel_launch(void* const* d_in, const int* in_sizes, int n_in,
                              void* d_out, int out_size) {
    const float* x   = (const float*)d_in[0];
    const int*   ni  = (const int*)  d_in[1];
    const int*   ei  = (const int*)  d_in[2];
    const float* W1  = (const float*)d_in[3];
    const float* b1  = (const float*)d_in[4];
    const float* W2  = (const float*)d_in[5];
    const float* b2  = (const float*)d_in[6];
    const float* Wm1 = (const float*)d_in[7];
    const float* bm1 = (const float*)d_in[8];
    const float* Wm2 = (const float*)d_in[9];
    const float* bm2 = (const float*)d_in[10];
    float* out = (float*)d_out;
    (void)in_sizes; (void)n_in; (void)out_size;

    cudaFuncSetAttribute(gemm_tf32_relu_kernel,
                         cudaFuncAttributeMaxDynamicSharedMemorySize, GEMM_SMEM_BYTES);
    cudaFuncSetAttribute(fused_mlp_softmax_kernel,
                         cudaFuncAttributeMaxDynamicSharedMemorySize, GEMM_SMEM_BYTES);

    __nv_bfloat16* xb;    cudaGetSymbolAddress((void**)&xb,    g_xb);
    __nv_bfloat16* efeat; cudaGetSymbolAddress((void**)&efeat, g_efeat);
    __nv_bfloat16* agg;   cudaGetSymbolAddress((void**)&agg,   g_agg);
    __nv_bfloat16* h1;    cudaGetSymbolAddress((void**)&h1,    g_h1);
    __nv_bfloat16* h2;    cudaGetSymbolAddress((void**)&h2,    g_h2);
    int* ecnt;  cudaGetSymbolAddress((void**)&ecnt,  g_ecnt);
    int* ncnt;  cudaGetSymbolAddress((void**)&ncnt,  g_ncnt);
    int* eoff;  cudaGetSymbolAddress((void**)&eoff,  g_eoff);
    int* noff;  cudaGetSymbolAddress((void**)&noff,  g_noff);
    int* ecur;  cudaGetSymbolAddress((void**)&ecur,  g_ecur);
    int* ncur;  cudaGetSymbolAddress((void**)&ncur,  g_ncur);
    int* epins; cudaGetSymbolAddress((void**)&epins, g_epins);
    int* npins; cudaGetSymbolAddress((void**)&npins, g_npins);
    int* esums; cudaGetSymbolAddress((void**)&esums, g_esums);
    int* nsums; cudaGetSymbolAddress((void**)&nsums, g_nsums);

    // ---- CSR build + x conversion ----
    zero_counts_kernel<<<512, 256>>>();
    count_kernel<<<(NNZV + 255) / 256, 256>>>(ni, ei);
    f2bf_kernel<<<2048, 256>>>(x, xb, NN * D / 4);
    scan_block_kernel<<<EBLK, 256>>>(ecnt, NE, eoff, esums);
    scan_block_kernel<<<NBLK, 256>>>(ncnt, NN, noff, nsums);
    scan_sums_kernel<<<2, 256>>>();
    scan_add_kernel<<<(NE + 255) / 256, 256>>>(eoff, ecur, esums, NE);
    scan_add_kernel<<<(NN + 255) / 256, 256>>>(noff, ncur, nsums, NN);
    fill_kernel<<<(NNZV + 255) / 256, 256>>>(ni, ei);

    const int egrid = (NE + 7) / 8;
    const int ngrid = (NN + 7) / 8;
    const int ggrid = (NN + 127) / 128;

    // ---- hconv layer 1 ----
    seg_mean_gather_kernel<<<egrid, 256>>>(xb, efeat, eoff, ecnt, epins, NE);
    seg_mean_gather_kernel<<<ngrid, 256>>>(efeat, agg, noff, ncnt, npins, NN);
    gemm_tf32_relu_kernel<<<ggrid, 256, GEMM_SMEM_BYTES>>>(agg, W1, b1, h1, NN);

    // ---- hconv layer 2 ----
    seg_mean_gather_kernel<<<egrid, 256>>>(h1, efeat, eoff, ecnt, epins, NE);
    seg_mean_gather_kernel<<<ngrid, 256>>>(efeat, agg, noff, ncnt, npins, NN);
    gemm_tf32_relu_kernel<<<ggrid, 256, GEMM_SMEM_BYTES>>>(agg, W2, b2, h2, NN);

    // ---- fused MLP + softmax ----
    fused_mlp_softmax_kernel<<<ggrid, 256, GEMM_SMEM_BYTES>>>(
        h2, Wm1, bm1, Wm2, bm2, out, NN);
}

// round 6
// speedup vs baseline: 2.6087x; 1.0091x over previous
#include <cuda_runtime.h>
#include <cuda_bf16.h>
#include <cstdint>

#define NN   100000   // nodes
#define NE   200000   // hyperedges
#define NNZV 800000   // pins
#define D    128
#define P    32

#define EBLK ((NE + 1023) / 1024)
#define NBLK ((NN + 1023) / 1024)

#define KPAD2 68      // smem stride (uint32) for packed bf16x2 weights / t-tile
#define APAD2 20      // smem stride (uint32) for packed bf16x2 A chunks

// ---------------- scratch (device globals; no allocation allowed) -----------
__device__ __nv_bfloat16 g_xb[(size_t)NN * D];
__device__ __nv_bfloat16 g_efeat[(size_t)NE * D];
__device__ __nv_bfloat16 g_agg[(size_t)NN * D];
__device__ __nv_bfloat16 g_h1[(size_t)NN * D];
__device__ __nv_bfloat16 g_h2[(size_t)NN * D];
__device__ int   g_ecnt[NE];
__device__ int   g_ncnt[NN];
__device__ int   g_eoff[NE];
__device__ int   g_noff[NN];
__device__ int   g_ecur[NE];
__device__ int   g_ncur[NN];
__device__ int   g_epins[NNZV];
__device__ int   g_npins[NNZV];
__device__ int   g_esums[256];
__device__ int   g_nsums[256];

// ---------------- CSR build ---------------------------------------------------
__global__ void zero_counts_kernel() {
    int i = blockIdx.x * blockDim.x + threadIdx.x;
    int stride = gridDim.x * blockDim.x;
    for (int t = i; t < NE; t += stride) g_ecnt[t] = 0;
    for (int t = i; t < NN; t += stride) g_ncnt[t] = 0;
}

__global__ void count_kernel(const int* __restrict__ ni, const int* __restrict__ ei) {
    int t = blockIdx.x * blockDim.x + threadIdx.x;
    if (t < NNZV) {
        atomicAdd(&g_ecnt[ei[t]], 1);
        atomicAdd(&g_ncnt[ni[t]], 1);
    }
}

// Combined edge+node block scan: blocks [0,EBLK) edges, [EBLK,EBLK+NBLK) nodes.
__global__ void __launch_bounds__(256) scan_block_kernel() {
    const int* cnt; int n; int* outp; int* sums; int bb;
    if (blockIdx.x < EBLK) { cnt = g_ecnt; n = NE; outp = g_eoff; sums = g_esums; bb = blockIdx.x; }
    else                   { cnt = g_ncnt; n = NN; outp = g_noff; sums = g_nsums; bb = blockIdx.x - EBLK; }
    __shared__ int sm[256];
    int tid = threadIdx.x;
    int base = bb * 1024 + tid * 4;
    int v[4]; int s = 0;
#pragma unroll
    for (int i = 0; i < 4; i++) {
        int idx = base + i;
        v[i] = (idx < n) ? cnt[idx] : 0;
        s += v[i];
    }
    sm[tid] = s; __syncthreads();
    for (int off = 1; off < 256; off <<= 1) {
        int u = (tid >= off) ? sm[tid - off] : 0;
        __syncthreads();
        sm[tid] += u;
        __syncthreads();
    }
    int excl = sm[tid] - s;
    if (tid == 255) sums[bb] = sm[255];
    int run = excl;
#pragma unroll
    for (int i = 0; i < 4; i++) {
        int idx = base + i;
        if (idx < n) outp[idx] = run;
        run += v[i];
    }
}

__global__ void __launch_bounds__(256) scan_sums_kernel() {
    int* sums = (blockIdx.x == 0) ? g_esums : g_nsums;
    int nb    = (blockIdx.x == 0) ? EBLK : NBLK;
    __shared__ int sm[256];
    int tid = threadIdx.x;
    int s = (tid < nb) ? sums[tid] : 0;
    sm[tid] = s; __syncthreads();
    for (int off = 1; off < 256; off <<= 1) {
        int u = (tid >= off) ? sm[tid - off] : 0;
        __syncthreads();
        sm[tid] += u;
        __syncthreads();
    }
    sums[tid] = sm[tid];
}

// Combined add-back for edges then nodes (idx space NE+NN).
__global__ void scan_add_kernel() {
    int idx = blockIdx.x * blockDim.x + threadIdx.x;
    if (idx < NE) {
        int b = idx >> 10;
        int add = (b > 0) ? g_esums[b - 1] : 0;
        int v = g_eoff[idx] + add;
        g_eoff[idx] = v; g_ecur[idx] = v;
    } else if (idx < NE + NN) {
        int i2 = idx - NE;
        int b = i2 >> 10;
        int add = (b > 0) ? g_nsums[b - 1] : 0;
        int v = g_noff[i2] + add;
        g_noff[i2] = v; g_ncur[i2] = v;
    }
}

__global__ void fill_kernel(const int* __restrict__ ni, const int* __restrict__ ei) {
    int t = blockIdx.x * blockDim.x + threadIdx.x;
    if (t < NNZV) {
        int n = ni[t], e = ei[t];
        g_epins[atomicAdd(&g_ecur[e], 1)] = n;
        g_npins[atomicAdd(&g_ncur[n], 1)] = e;
    }
}

// ---------------- fp32 -> bf16 convert ---------------------------------------
__global__ void __launch_bounds__(256)
f2bf_kernel(const float* __restrict__ src, __nv_bfloat16* __restrict__ dst, int n4) {
    int i = blockIdx.x * blockDim.x + threadIdx.x;
    int stride = gridDim.x * blockDim.x;
    const float4* s4 = (const float4*)src;
    uint2* d2 = (uint2*)dst;
    for (int t = i; t < n4; t += stride) {
        float4 v = __ldg(&s4[t]);
        __nv_bfloat162 lo = __float22bfloat162_rn(make_float2(v.x, v.y));
        __nv_bfloat162 hi = __float22bfloat162_rn(make_float2(v.z, v.w));
        uint2 o;
        o.x = *(uint32_t*)&lo;
        o.y = *(uint32_t*)&hi;
        d2[t] = o;
    }
}

// ---------------- segment-mean gather: 4 pins in flight per warp -------------
// Row = 128 bf16 = 256B = 16 uint4. Quarter-warp (8 lanes) covers one row:
// lane l8 loads uint4 cols l8 and l8+8. Quad q processes pins k+q.
__global__ void __launch_bounds__(256)
seg_mean_gather_kernel(const __nv_bfloat16* __restrict__ src,
                       __nv_bfloat16* __restrict__ dst,
                       const int* __restrict__ offs, const int* __restrict__ cnts,
                       const int* __restrict__ pins, int nseg) {
    int w = blockIdx.x * 8 + (threadIdx.x >> 5);
    if (w >= nseg) return;
    int lane = threadIdx.x & 31;
    int quad = lane >> 3;    // which pin within group of 4
    int l8   = lane & 7;     // position within row
    int off = __ldg(&offs[w]);
    int deg = __ldg(&cnts[w]);
    const uint4* s4 = (const uint4*)src;   // 16 uint4 per row
    float acc[16];
#pragma unroll
    for (int i = 0; i < 16; i++) acc[i] = 0.f;

    for (int j = 0; j < deg; j += 32) {
        int rem = deg - j;
        int idx = (lane < rem) ? __ldg(&pins[off + j + lane]) : 0;
        int kmax = rem < 32 ? rem : 32;
        for (int k = 0; k < kmax; k += 4) {
            int kk = k + quad;
            int r = __shfl_sync(0xffffffffu, idx, kk);
            if (kk < kmax) {
                const uint4* rp = &s4[(size_t)r * 16];
                uint4 v0 = __ldg(&rp[l8]);
                uint4 v1 = __ldg(&rp[l8 + 8]);
                float2 t;
                t = __bfloat1622float2(*(__nv_bfloat162*)&v0.x); acc[0] += t.x; acc[1] += t.y;
                t = __bfloat1622float2(*(__nv_bfloat162*)&v0.y); acc[2] += t.x; acc[3] += t.y;
                t = __bfloat1622float2(*(__nv_bfloat162*)&v0.z); acc[4] += t.x; acc[5] += t.y;
                t = __bfloat1622float2(*(__nv_bfloat162*)&v0.w); acc[6] += t.x; acc[7] += t.y;
                t = __bfloat1622float2(*(__nv_bfloat162*)&v1.x); acc[8] += t.x; acc[9] += t.y;
                t = __bfloat1622float2(*(__nv_bfloat162*)&v1.y); acc[10] += t.x; acc[11] += t.y;
                t = __bfloat1622float2(*(__nv_bfloat162*)&v1.z); acc[12] += t.x; acc[13] += t.y;
                t = __bfloat1622float2(*(__nv_bfloat162*)&v1.w); acc[14] += t.x; acc[15] += t.y;
            }
        }
    }
    // combine quads (lanes sharing l8): xor 8 then 16
#pragma unroll
    for (int i = 0; i < 16; i++) {
        acc[i] += __shfl_xor_sync(0xffffffffu, acc[i], 8);
        acc[i] += __shfl_xor_sync(0xffffffffu, acc[i], 16);
    }
    if (quad == 0) {
        float sc = 1.0f / (float)(deg > 0 ? deg : 1);
        uint4 o0, o1;
        __nv_bfloat162 b2;
#define PK(dst_, a_, b_) b2 = __float22bfloat162_rn(make_float2((a_) * sc, (b_) * sc)); dst_ = *(uint32_t*)&b2;
        PK(o0.x, acc[0], acc[1]) PK(o0.y, acc[2], acc[3])
        PK(o0.z, acc[4], acc[5]) PK(o0.w, acc[6], acc[7])
        PK(o1.x, acc[8], acc[9]) PK(o1.y, acc[10], acc[11])
        PK(o1.z, acc[12], acc[13]) PK(o1.w, acc[14], acc[15])
#undef PK
        uint4* d = (uint4*)dst + (size_t)w * 16;
        d[l8] = o0;
        d[l8 + 8] = o1;
    }
}

// ---------------- bf16 mma helpers -------------------------------------------
__device__ __forceinline__ void mma_bf16(float* c,
                                         uint32_t a0, uint32_t a1, uint32_t a2, uint32_t a3,
                                         uint32_t b0, uint32_t b1) {
    asm volatile("mma.sync.aligned.m16n8k16.row.col.f32.bf16.bf16.f32 "
                 "{%0,%1,%2,%3}, {%4,%5,%6,%7}, {%8,%9}, {%0,%1,%2,%3};"
                 : "+f"(c[0]), "+f"(c[1]), "+f"(c[2]), "+f"(c[3])
                 : "r"(a0), "r"(a1), "r"(a2), "r"(a3), "r"(b0), "r"(b1));
}

__device__ __forceinline__ uint32_t packbf(float a, float b) {
    __nv_bfloat162 v = __float22bfloat162_rn(make_float2(a, b));
    return *(uint32_t*)&v;
}

#define GEMM_SMEM_BYTES ((128 * KPAD2 + 128 * APAD2) * 4)

// Mainloop: acc[16][4] += in_tile(128x128 bf16) @ W(bf16 packed in WsT).
// WsT: [n][KPAD2] uint32, element kk packs W[2kk][n],W[2kk+1][n].
// As:  [r][APAD2] uint32, element kk packs A[r][2kk],A[r][2kk+1] (raw bf16 pairs).
__device__ __forceinline__ void gemm_mainloop(const __nv_bfloat16* __restrict__ in,
                                              int nrows,
                                              uint32_t* WsT, uint32_t* As,
                                              int row0, int warp, int lane,
                                              float acc[16][4]) {
    const int tid = threadIdx.x;
    const int wr = warp * 16;
    const int q = lane >> 2, p = lane & 3;
#pragma unroll
    for (int nf = 0; nf < 16; nf++)
#pragma unroll
        for (int j = 0; j < 4; j++) acc[nf][j] = 0.f;

    for (int kc = 0; kc < 4; kc++) {   // K chunks of 32 (16 packed)
        __syncthreads();
        for (int i = tid; i < 128 * 16; i += 256) {
            int r = i >> 4, c = i & 15;
            int gr = row0 + r;
            uint32_t v = 0;
            if (gr < nrows)
                v = __ldg((const uint32_t*)&in[(size_t)gr * 128 + kc * 32 + c * 2]);
            As[r * APAD2 + c] = v;
        }
        __syncthreads();
#pragma unroll
        for (int ks = 0; ks < 2; ks++) {   // two K=16 steps
            int kb = ks * 8;               // packed base within chunk
            uint32_t a0 = As[(wr + q) * APAD2 + kb + p];
            uint32_t a1 = As[(wr + q + 8) * APAD2 + kb + p];
            uint32_t a2 = As[(wr + q) * APAD2 + kb + p + 4];
            uint32_t a3 = As[(wr + q + 8) * APAD2 + kb + p + 4];
            int kg = kc * 16 + kb;         // packed global base
#pragma unroll
            for (int nf = 0; nf < 16; nf++) {
                uint32_t b0 = WsT[(nf * 8 + q) * KPAD2 + kg + p];
                uint32_t b1 = WsT[(nf * 8 + q) * KPAD2 + kg + p + 4];
                mma_bf16(acc[nf], a0, a1, a2, a3, b0, b1);
            }
        }
    }
}

// ---------------- GEMM(128x128) + bias + ReLU -> bf16 ------------------------
__global__ void __launch_bounds__(256)
gemm_bf16_relu_kernel(const __nv_bfloat16* __restrict__ in,
                      const float* __restrict__ W, const float* __restrict__ b,
                      __nv_bfloat16* __restrict__ out, int nrows) {
    extern __shared__ uint32_t smu[];
    uint32_t* WsT = smu;                   // [128][KPAD2]
    uint32_t* As  = smu + 128 * KPAD2;     // [128][APAD2]
    const int tid = threadIdx.x;

    for (int i = tid; i < 128 * 64; i += 256) {
        int kk = i >> 7, n = i & 127;
        float w0 = __ldg(&W[(2 * kk) * 128 + n]);
        float w1 = __ldg(&W[(2 * kk + 1) * 128 + n]);
        WsT[n * KPAD2 + kk] = packbf(w0, w1);
    }
    int row0 = blockIdx.x * 128;
    int warp = tid >> 5, lane = tid & 31;
    float acc[16][4];
    gemm_mainloop(in, nrows, WsT, As, row0, warp, lane, acc);

    const int q = lane >> 2, p = lane & 3;
    int r_lo = row0 + warp * 16 + q;
    int r_hi = r_lo + 8;
#pragma unroll
    for (int nf = 0; nf < 16; nf++) {
        int c = nf * 8 + 2 * p;
        float bx = __ldg(&b[c]), by = __ldg(&b[c + 1]);
        if (r_lo < nrows)
            *(uint32_t*)&out[(size_t)r_lo * 128 + c] =
                packbf(fmaxf(acc[nf][0] + bx, 0.f), fmaxf(acc[nf][1] + by, 0.f));
        if (r_hi < nrows)
            *(uint32_t*)&out[(size_t)r_hi * 128 + c] =
                packbf(fmaxf(acc[nf][2] + bx, 0.f), fmaxf(acc[nf][3] + by, 0.f));
    }
}

// ---------------- fused: relu(in@Wm1+bm1) @ Wm2 + bm2, softmax ---------------
__global__ void __launch_bounds__(256)
fused_mlp_softmax_kernel(const __nv_bfloat16* __restrict__ in,
                         const float* __restrict__ Wm1, const float* __restrict__ bm1,
                         const float* __restrict__ Wm2, const float* __restrict__ bm2,
                         float* __restrict__ out, int nrows) {
    extern __shared__ uint32_t smu[];
    uint32_t* WsT = smu;                   // [128][KPAD2]; later t-tile
    uint32_t* As  = smu + 128 * KPAD2;     // [128][APAD2]; later Wm2T
    __shared__ float bs2[P];
    const int tid = threadIdx.x;

    for (int i = tid; i < 128 * 64; i += 256) {
        int kk = i >> 7, n = i & 127;
        float w0 = __ldg(&Wm1[(2 * kk) * 128 + n]);
        float w1 = __ldg(&Wm1[(2 * kk + 1) * 128 + n]);
        WsT[n * KPAD2 + kk] = packbf(w0, w1);
    }
    if (tid < P) bs2[tid] = bm2[tid];

    int row0 = blockIdx.x * 128;
    int warp = tid >> 5, lane = tid & 31;
    const int wr = warp * 16;
    const int q = lane >> 2, p = lane & 3;
    float acc[16][4];
    gemm_mainloop(in, nrows, WsT, As, row0, warp, lane, acc);

    __syncthreads();
    uint32_t* Ts   = WsT;  // [128 rows][KPAD2] packed bf16x2
    uint32_t* W2sT = As;   // [32 n][KPAD2]  (32*68*4 = 8704 <= 128*20*4)
#pragma unroll
    for (int nf = 0; nf < 16; nf++) {
        int c = nf * 8 + 2 * p;            // even column
        float bx = __ldg(&bm1[c]), by = __ldg(&bm1[c + 1]);
        Ts[(wr + q) * KPAD2 + nf * 4 + p] =
            packbf(fmaxf(acc[nf][0] + bx, 0.f), fmaxf(acc[nf][1] + by, 0.f));
        Ts[(wr + q + 8) * KPAD2 + nf * 4 + p] =
            packbf(fmaxf(acc[nf][2] + bx, 0.f), fmaxf(acc[nf][3] + by, 0.f));
    }
    for (int i = tid; i < 32 * 64; i += 256) {
        int kk = i >> 5, n = i & 31;
        float w0 = __ldg(&Wm2[(2 * kk) * 32 + n]);
        float w1 = __ldg(&Wm2[(2 * kk + 1) * 32 + n]);
        W2sT[n * KPAD2 + kk] = packbf(w0, w1);
    }
    __syncthreads();

    float acc2[4][4];
#pragma unroll
    for (int nf = 0; nf < 4; nf++)
#pragma unroll
        for (int j = 0; j < 4; j++) acc2[nf][j] = 0.f;
#pragma unroll
    for (int ks = 0; ks < 8; ks++) {       // K=128 in 8 steps of 16
        int kb = ks * 8;
        uint32_t a0 = Ts[(wr + q) * KPAD2 + kb + p];
        uint32_t a1 = Ts[(wr + q + 8) * KPAD2 + kb + p];
        uint32_t a2 = Ts[(wr + q) * KPAD2 + kb + p + 4];
        uint32_t a3 = Ts[(wr + q + 8) * KPAD2 + kb + p + 4];
#pragma unroll
        for (int nf = 0; nf < 4; nf++) {
            uint32_t b0 = W2sT[(nf * 8 + q) * KPAD2 + kb + p];
            uint32_t b1 = W2sT[(nf * 8 + q) * KPAD2 + kb + p + 4];
            mma_bf16(acc2[nf], a0, a1, a2, a3, b0, b1);
        }
    }

    float vlo[8], vhi[8];
#pragma unroll
    for (int nf = 0; nf < 4; nf++) {
        int c = nf * 8 + 2 * p;
        vlo[nf * 2]     = acc2[nf][0] + bs2[c];
        vlo[nf * 2 + 1] = acc2[nf][1] + bs2[c + 1];
        vhi[nf * 2]     = acc2[nf][2] + bs2[c];
        vhi[nf * 2 + 1] = acc2[nf][3] + bs2[c + 1];
    }
    float mlo = vlo[0], mhi = vhi[0];
#pragma unroll
    for (int j = 1; j < 8; j++) { mlo = fmaxf(mlo, vlo[j]); mhi = fmaxf(mhi, vhi[j]); }
    mlo = fmaxf(mlo, __shfl_xor_sync(0xffffffffu, mlo, 1));
    mlo = fmaxf(mlo, __shfl_xor_sync(0xffffffffu, mlo, 2));
    mhi = fmaxf(mhi, __shfl_xor_sync(0xffffffffu, mhi, 1));
    mhi = fmaxf(mhi, __shfl_xor_sync(0xffffffffu, mhi, 2));
    float slo = 0.f, shi = 0.f;
#pragma unroll
    for (int j = 0; j < 8; j++) {
        vlo[j] = __expf(vlo[j] - mlo); slo += vlo[j];
        vhi[j] = __expf(vhi[j] - mhi); shi += vhi[j];
    }
    slo += __shfl_xor_sync(0xffffffffu, slo, 1);
    slo += __shfl_xor_sync(0xffffffffu, slo, 2);
    shi += __shfl_xor_sync(0xffffffffu, shi, 1);
    shi += __shfl_xor_sync(0xffffffffu, shi, 2);
    float rlo = 1.f / slo, rhi = 1.f / shi;

    int r_lo = row0 + wr + q;
    int r_hi = r_lo + 8;
#pragma unroll
    for (int nf = 0; nf < 4; nf++) {
        int c = nf * 8 + 2 * p;
        if (r_lo < nrows)
            *(float2*)&out[(size_t)r_lo * P + c] =
                make_float2(vlo[nf * 2] * rlo, vlo[nf * 2 + 1] * rlo);
        if (r_hi < nrows)
            *(float2*)&out[(size_t)r_hi * P + c] =
                make_float2(vhi[nf * 2] * rhi, vhi[nf * 2 + 1] * rhi);
    }
}

// ---------------- launch ------------------------------------------------------
extern "C" void kernel_launch(void* const* d_in, const int* in_sizes, int n_in,
                              void* d_out, int out_size) {
    const float* x   = (const float*)d_in[0];
    const int*   ni  = (const int*)  d_in[1];
    const int*   ei  = (const int*)  d_in[2];
    const float* W1  = (const float*)d_in[3];
    const float* b1  = (const float*)d_in[4];
    const float* W2  = (const float*)d_in[5];
    const float* b2  = (const float*)d_in[6];
    const float* Wm1 = (const float*)d_in[7];
    const float* bm1 = (const float*)d_in[8];
    const float* Wm2 = (const float*)d_in[9];
    const float* bm2 = (const float*)d_in[10];
    float* out = (float*)d_out;
    (void)in_sizes; (void)n_in; (void)out_size;

    cudaFuncSetAttribute(gemm_bf16_relu_kernel,
                         cudaFuncAttributeMaxDynamicSharedMemorySize, GEMM_SMEM_BYTES);
    cudaFuncSetAttribute(fused_mlp_softmax_kernel,
                         cudaFuncAttributeMaxDynamicSharedMemorySize, GEMM_SMEM_BYTES);

    __nv_bfloat16* xb;    cudaGetSymbolAddress((void**)&xb,    g_xb);
    __nv_bfloat16* efeat; cudaGetSymbolAddress((void**)&efeat, g_efeat);
    __nv_bfloat16* agg;   cudaGetSymbolAddress((void**)&agg,   g_agg);
    __nv_bfloat16* h1;    cudaGetSymbolAddress((void**)&h1,    g_h1);
    __nv_bfloat16* h2;    cudaGetSymbolAddress((void**)&h2,    g_h2);
    int* ecnt;  cudaGetSymbolAddress((void**)&ecnt,  g_ecnt);
    int* ncnt;  cudaGetSymbolAddress((void**)&ncnt,  g_ncnt);
    int* eoff;  cudaGetSymbolAddress((void**)&eoff,  g_eoff);
    int* noff;  cudaGetSymbolAddress((void**)&noff,  g_noff);
    int* epins; cudaGetSymbolAddress((void**)&epins, g_epins);
    int* npins; cudaGetSymbolAddress((void**)&npins, g_npins);

    // ---- CSR build + x conversion ----
    zero_counts_kernel<<<512, 256>>>();
    count_kernel<<<(NNZV + 255) / 256, 256>>>(ni, ei);
    f2bf_kernel<<<2048, 256>>>(x, xb, NN * D / 4);
    scan_block_kernel<<<EBLK + NBLK, 256>>>();
    scan_sums_kernel<<<2, 256>>>();
    scan_add_kernel<<<(NE + NN + 255) / 256, 256>>>();
    fill_kernel<<<(NNZV + 255) / 256, 256>>>(ni, ei);

    const int egrid = (NE + 7) / 8;
    const int ngrid = (NN + 7) / 8;
    const int ggrid = (NN + 127) / 128;

    // ---- hconv layer 1 ----
    seg_mean_gather_kernel<<<egrid, 256>>>(xb, efeat, eoff, ecnt, epins, NE);
    seg_mean_gather_kernel<<<ngrid, 256>>>(efeat, agg, noff, ncnt, npins, NN);
    gemm_bf16_relu_kernel<<<ggrid, 256, GEMM_SMEM_BYTES>>>(agg, W1, b1, h1, NN);

    // ---- hconv layer 2 ----
    seg_mean_gather_kernel<<<egrid, 256>>>(h1, efeat, eoff, ecnt, epins, NE);
    seg_mean_gather_kernel<<<ngrid, 256>>>(efeat, agg, noff, ncnt, npins, NN);
    gemm_bf16_relu_kernel<<<ggrid, 256, GEMM_SMEM_BYTES>>>(agg, W2, b2, h2, NN);

    // ---- fused MLP + softmax ----
    fused_mlp_softmax_kernel<<<ggrid, 256, GEMM_SMEM_BYTES>>>(
        h2, Wm1, bm1, Wm2, bm2, out, NN);
}

// round 7
// speedup vs baseline: 2.7824x; 1.0666x over previous
#include <cuda_runtime.h>
#include <cuda_bf16.h>
#include <cstdint>

#define NN   100000   // nodes
#define NE   200000   // hyperedges
#define NNZV 800000   // pins
#define D    128
#define P    32

#define EBLK ((NE + 1023) / 1024)
#define NBLK ((NN + 1023) / 1024)

#define SOF 68        // smem stride (uint32) for packed bf16x2 full tiles
#define SMEM_BYTES (128 * SOF * 2 * 4)   // WsT + As = 69632 B

// ---------------- scratch ----------------------------------------------------
__device__ __nv_bfloat16 g_xb[(size_t)NN * D];
__device__ __nv_bfloat16 g_efeat[(size_t)NE * D];
__device__ __nv_bfloat16 g_h1[(size_t)NN * D];
__device__ int   g_ecnt[NE];
__device__ int   g_ncnt[NN];
__device__ int   g_eoff[NE];
__device__ int   g_noff[NN];
__device__ int   g_ecur[NE];
__device__ int   g_ncur[NN];
__device__ int   g_epins[NNZV];
__device__ int   g_npins[NNZV];
__device__ int   g_esums[256];
__device__ int   g_nsums[256];

// ---------------- merged zero-counts + x->bf16 -------------------------------
__global__ void __launch_bounds__(256)
zf_kernel(const float* __restrict__ x) {
    int i = blockIdx.x * blockDim.x + threadIdx.x;
    int stride = gridDim.x * blockDim.x;
    for (int t = i; t < NE; t += stride) g_ecnt[t] = 0;
    for (int t = i; t < NN; t += stride) g_ncnt[t] = 0;
    const float4* s4 = (const float4*)x;
    uint2* d2 = (uint2*)g_xb;
    const int n4 = NN * D / 4;
    for (int t = i; t < n4; t += stride) {
        float4 v = __ldg(&s4[t]);
        __nv_bfloat162 lo = __float22bfloat162_rn(make_float2(v.x, v.y));
        __nv_bfloat162 hi = __float22bfloat162_rn(make_float2(v.z, v.w));
        uint2 o;
        o.x = *(uint32_t*)&lo;
        o.y = *(uint32_t*)&hi;
        d2[t] = o;
    }
}

__global__ void count_kernel(const int* __restrict__ ni, const int* __restrict__ ei) {
    int t = blockIdx.x * blockDim.x + threadIdx.x;
    if (t < NNZV) {
        atomicAdd(&g_ecnt[ei[t]], 1);
        atomicAdd(&g_ncnt[ni[t]], 1);
    }
}

__global__ void __launch_bounds__(256) scan_block_kernel() {
    const int* cnt; int n; int* outp; int* sums; int bb;
    if (blockIdx.x < EBLK) { cnt = g_ecnt; n = NE; outp = g_eoff; sums = g_esums; bb = blockIdx.x; }
    else                   { cnt = g_ncnt; n = NN; outp = g_noff; sums = g_nsums; bb = blockIdx.x - EBLK; }
    __shared__ int sm[256];
    int tid = threadIdx.x;
    int base = bb * 1024 + tid * 4;
    int v[4]; int s = 0;
#pragma unroll
    for (int i = 0; i < 4; i++) {
        int idx = base + i;
        v[i] = (idx < n) ? cnt[idx] : 0;
        s += v[i];
    }
    sm[tid] = s; __syncthreads();
    for (int off = 1; off < 256; off <<= 1) {
        int u = (tid >= off) ? sm[tid - off] : 0;
        __syncthreads();
        sm[tid] += u;
        __syncthreads();
    }
    int excl = sm[tid] - s;
    if (tid == 255) sums[bb] = sm[255];
    int run = excl;
#pragma unroll
    for (int i = 0; i < 4; i++) {
        int idx = base + i;
        if (idx < n) outp[idx] = run;
        run += v[i];
    }
}

__global__ void __launch_bounds__(256) scan_sums_kernel() {
    int* sums = (blockIdx.x == 0) ? g_esums : g_nsums;
    int nb    = (blockIdx.x == 0) ? EBLK : NBLK;
    __shared__ int sm[256];
    int tid = threadIdx.x;
    int s = (tid < nb) ? sums[tid] : 0;
    sm[tid] = s; __syncthreads();
    for (int off = 1; off < 256; off <<= 1) {
        int u = (tid >= off) ? sm[tid - off] : 0;
        __syncthreads();
        sm[tid] += u;
        __syncthreads();
    }
    sums[tid] = sm[tid];
}

__global__ void scan_add_kernel() {
    int idx = blockIdx.x * blockDim.x + threadIdx.x;
    if (idx < NE) {
        int b = idx >> 10;
        int add = (b > 0) ? g_esums[b - 1] : 0;
        int v = g_eoff[idx] + add;
        g_eoff[idx] = v; g_ecur[idx] = v;
    } else if (idx < NE + NN) {
        int i2 = idx - NE;
        int b = i2 >> 10;
        int add = (b > 0) ? g_nsums[b - 1] : 0;
        int v = g_noff[i2] + add;
        g_noff[i2] = v; g_ncur[i2] = v;
    }
}

__global__ void fill_kernel(const int* __restrict__ ni, const int* __restrict__ ei) {
    int t = blockIdx.x * blockDim.x + threadIdx.x;
    if (t < NNZV) {
        int n = ni[t], e = ei[t];
        g_epins[atomicAdd(&g_ecur[e], 1)] = n;
        g_npins[atomicAdd(&g_ncur[n], 1)] = e;
    }
}

// ---------------- helpers -----------------------------------------------------
__device__ __forceinline__ uint32_t packbf(float a, float b) {
    __nv_bfloat162 v = __float22bfloat162_rn(make_float2(a, b));
    return *(uint32_t*)&v;
}

__device__ __forceinline__ void mma_bf16(float* c,
                                         uint32_t a0, uint32_t a1, uint32_t a2, uint32_t a3,
                                         uint32_t b0, uint32_t b1) {
    asm volatile("mma.sync.aligned.m16n8k16.row.col.f32.bf16.bf16.f32 "
                 "{%0,%1,%2,%3}, {%4,%5,%6,%7}, {%8,%9}, {%0,%1,%2,%3};"
                 : "+f"(c[0]), "+f"(c[1]), "+f"(c[2]), "+f"(c[3])
                 : "r"(a0), "r"(a1), "r"(a2), "r"(a3), "r"(b0), "r"(b1));
}

// ---------------- standalone edge gather (bf16, 4 pins in flight) ------------
__global__ void __launch_bounds__(256)
seg_mean_gather_kernel(const __nv_bfloat16* __restrict__ src,
                       __nv_bfloat16* __restrict__ dst,
                       const int* __restrict__ offs, const int* __restrict__ cnts,
                       const int* __restrict__ pins, int nseg) {
    int w = blockIdx.x * 8 + (threadIdx.x >> 5);
    if (w >= nseg) return;
    int lane = threadIdx.x & 31;
    int quad = lane >> 3;
    int l8   = lane & 7;
    int off = __ldg(&offs[w]);
    int deg = __ldg(&cnts[w]);
    const uint4* s4 = (const uint4*)src;
    float acc[16];
#pragma unroll
    for (int i = 0; i < 16; i++) acc[i] = 0.f;

    for (int j = 0; j < deg; j += 32) {
        int rem = deg - j;
        int idx = (lane < rem) ? __ldg(&pins[off + j + lane]) : 0;
        int kmax = rem < 32 ? rem : 32;
        for (int k = 0; k < kmax; k += 4) {
            int kk = k + quad;
            int r = __shfl_sync(0xffffffffu, idx, kk);
            if (kk < kmax) {
                const uint4* rp = &s4[(size_t)r * 16];
                uint4 v0 = __ldg(&rp[l8]);
                uint4 v1 = __ldg(&rp[l8 + 8]);
                float2 t;
                t = __bfloat1622float2(*(__nv_bfloat162*)&v0.x); acc[0] += t.x; acc[1] += t.y;
                t = __bfloat1622float2(*(__nv_bfloat162*)&v0.y); acc[2] += t.x; acc[3] += t.y;
                t = __bfloat1622float2(*(__nv_bfloat162*)&v0.z); acc[4] += t.x; acc[5] += t.y;
                t = __bfloat1622float2(*(__nv_bfloat162*)&v0.w); acc[6] += t.x; acc[7] += t.y;
                t = __bfloat1622float2(*(__nv_bfloat162*)&v1.x); acc[8] += t.x; acc[9] += t.y;
                t = __bfloat1622float2(*(__nv_bfloat162*)&v1.y); acc[10] += t.x; acc[11] += t.y;
                t = __bfloat1622float2(*(__nv_bfloat162*)&v1.z); acc[12] += t.x; acc[13] += t.y;
                t = __bfloat1622float2(*(__nv_bfloat162*)&v1.w); acc[14] += t.x; acc[15] += t.y;
            }
        }
    }
#pragma unroll
    for (int i = 0; i < 16; i++) {
        acc[i] += __shfl_xor_sync(0xffffffffu, acc[i], 8);
        acc[i] += __shfl_xor_sync(0xffffffffu, acc[i], 16);
    }
    if (quad == 0) {
        float sc = 1.0f / (float)(deg > 0 ? deg : 1);
        uint4 o0, o1;
#define PK(dst_, a_, b_) dst_ = packbf((a_) * sc, (b_) * sc);
        PK(o0.x, acc[0], acc[1]) PK(o0.y, acc[2], acc[3])
        PK(o0.z, acc[4], acc[5]) PK(o0.w, acc[6], acc[7])
        PK(o1.x, acc[8], acc[9]) PK(o1.y, acc[10], acc[11])
        PK(o1.z, acc[12], acc[13]) PK(o1.w, acc[14], acc[15])
#undef PK
        uint4* d = (uint4*)dst + (size_t)w * 16;
        d[l8] = o0;
        d[l8 + 8] = o1;
    }
}

// ---------------- device: gather node means directly into smem A tile --------
// Warp handles 16 consecutive rows; quad scheme; quad0 writes packed row to As.
__device__ __forceinline__ void gather_rows_to_smem(
    const __nv_bfloat16* __restrict__ src, uint32_t* As,
    const int* __restrict__ offs, const int* __restrict__ cnts,
    const int* __restrict__ pins, int nseg, int row0) {
    const int warp = threadIdx.x >> 5, lane = threadIdx.x & 31;
    const int quad = lane >> 3, l8 = lane & 7;
    const uint4* s4 = (const uint4*)src;
    for (int t = 0; t < 16; t++) {
        int rl = warp * 16 + t;
        int seg = row0 + rl;
        float acc[16];
#pragma unroll
        for (int i = 0; i < 16; i++) acc[i] = 0.f;
        int deg = 0;
        if (seg < nseg) {
            int off = __ldg(&offs[seg]);
            deg = __ldg(&cnts[seg]);
            for (int j = 0; j < deg; j += 32) {
                int rem = deg - j;
                int idx = (lane < rem) ? __ldg(&pins[off + j + lane]) : 0;
                int kmax = rem < 32 ? rem : 32;
                for (int k = 0; k < kmax; k += 4) {
                    int kk = k + quad;
                    int r = __shfl_sync(0xffffffffu, idx, kk);
                    if (kk < kmax) {
                        const uint4* rp = &s4[(size_t)r * 16];
                        uint4 v0 = __ldg(&rp[l8]);
                        uint4 v1 = __ldg(&rp[l8 + 8]);
                        float2 f;
                        f = __bfloat1622float2(*(__nv_bfloat162*)&v0.x); acc[0] += f.x; acc[1] += f.y;
                        f = __bfloat1622float2(*(__nv_bfloat162*)&v0.y); acc[2] += f.x; acc[3] += f.y;
                        f = __bfloat1622float2(*(__nv_bfloat162*)&v0.z); acc[4] += f.x; acc[5] += f.y;
                        f = __bfloat1622float2(*(__nv_bfloat162*)&v0.w); acc[6] += f.x; acc[7] += f.y;
                        f = __bfloat1622float2(*(__nv_bfloat162*)&v1.x); acc[8] += f.x; acc[9] += f.y;
                        f = __bfloat1622float2(*(__nv_bfloat162*)&v1.y); acc[10] += f.x; acc[11] += f.y;
                        f = __bfloat1622float2(*(__nv_bfloat162*)&v1.z); acc[12] += f.x; acc[13] += f.y;
                        f = __bfloat1622float2(*(__nv_bfloat162*)&v1.w); acc[14] += f.x; acc[15] += f.y;
                    }
                }
            }
        }
#pragma unroll
        for (int i = 0; i < 16; i++) {
            acc[i] += __shfl_xor_sync(0xffffffffu, acc[i], 8);
            acc[i] += __shfl_xor_sync(0xffffffffu, acc[i], 16);
        }
        if (quad == 0) {
            float sc = 1.0f / (float)(deg > 0 ? deg : 1);
            uint4 o0, o1;
#define PK(dst_, a_, b_) dst_ = packbf((a_) * sc, (b_) * sc);
            PK(o0.x, acc[0], acc[1]) PK(o0.y, acc[2], acc[3])
            PK(o0.z, acc[4], acc[5]) PK(o0.w, acc[6], acc[7])
            PK(o1.x, acc[8], acc[9]) PK(o1.y, acc[10], acc[11])
            PK(o1.z, acc[12], acc[13]) PK(o1.w, acc[14], acc[15])
#undef PK
            *(uint4*)&As[rl * SOF + 4 * l8]      = o0;
            *(uint4*)&As[rl * SOF + 32 + 4 * l8] = o1;
        }
    }
}

// ---------------- device: full-tile mma  acc += As(128x128) @ WsT ------------
__device__ __forceinline__ void mma_full(const uint32_t* As, const uint32_t* WsT,
                                         int warp, int lane, float acc[16][4],
                                         int nfrags) {
    const int wr = warp * 16;
    const int q = lane >> 2, p = lane & 3;
#pragma unroll
    for (int nf = 0; nf < 16; nf++)
#pragma unroll
        for (int j = 0; j < 4; j++) if (nf < nfrags) acc[nf][j] = 0.f;
#pragma unroll
    for (int ks = 0; ks < 8; ks++) {
        int kb = ks * 8;
        uint32_t a0 = As[(wr + q) * SOF + kb + p];
        uint32_t a1 = As[(wr + q + 8) * SOF + kb + p];
        uint32_t a2 = As[(wr + q) * SOF + kb + p + 4];
        uint32_t a3 = As[(wr + q + 8) * SOF + kb + p + 4];
#pragma unroll
        for (int nf = 0; nf < 16; nf++) {
            if (nf < nfrags) {
                uint32_t b0 = WsT[(nf * 8 + q) * SOF + kb + p];
                uint32_t b1 = WsT[(nf * 8 + q) * SOF + kb + p + 4];
                mma_bf16(acc[nf], a0, a1, a2, a3, b0, b1);
            }
        }
    }
}

__device__ __forceinline__ void load_w_tile(const float* __restrict__ W, uint32_t* WsT,
                                            int ncols) {
    // W row-major [128][ncols]; WsT[n][kk] packs W[2kk][n], W[2kk+1][n]
    for (int i = threadIdx.x; i < ncols * 64; i += 256) {
        int kk = i / ncols, n = i % ncols;
        float w0 = __ldg(&W[(2 * kk) * ncols + n]);
        float w1 = __ldg(&W[(2 * kk + 1) * ncols + n]);
        WsT[n * SOF + kk] = packbf(w0, w1);
    }
}

// ---------------- fused: node-gather + GEMM + bias + ReLU -> bf16 ------------
__global__ void __launch_bounds__(256)
ngather_gemm_kernel(const __nv_bfloat16* __restrict__ efeat,
                    const float* __restrict__ W, const float* __restrict__ b,
                    __nv_bfloat16* __restrict__ out, int nrows) {
    extern __shared__ uint32_t smu[];
    uint32_t* WsT = smu;
    uint32_t* As  = smu + 128 * SOF;
    const int tid = threadIdx.x;
    const int row0 = blockIdx.x * 128;
    const int warp = tid >> 5, lane = tid & 31;

    load_w_tile(W, WsT, 128);
    gather_rows_to_smem(efeat, As, g_noff, g_ncnt, g_npins, nrows, row0);
    __syncthreads();

    float acc[16][4];
    mma_full(As, WsT, warp, lane, acc, 16);

    const int q = lane >> 2, p = lane & 3;
    int r_lo = row0 + warp * 16 + q;
    int r_hi = r_lo + 8;
#pragma unroll
    for (int nf = 0; nf < 16; nf++) {
        int c = nf * 8 + 2 * p;
        float bx = __ldg(&b[c]), by = __ldg(&b[c + 1]);
        if (r_lo < nrows)
            *(uint32_t*)&out[(size_t)r_lo * 128 + c] =
                packbf(fmaxf(acc[nf][0] + bx, 0.f), fmaxf(acc[nf][1] + by, 0.f));
        if (r_hi < nrows)
            *(uint32_t*)&out[(size_t)r_hi * 128 + c] =
                packbf(fmaxf(acc[nf][2] + bx, 0.f), fmaxf(acc[nf][3] + by, 0.f));
    }
}

// ---------------- fused: node-gather + W2 + Wm1 + Wm2 + softmax -> out -------
__global__ void __launch_bounds__(256)
ngather_gemm_mlp_kernel(const __nv_bfloat16* __restrict__ efeat,
                        const float* __restrict__ W2, const float* __restrict__ b2,
                        const float* __restrict__ Wm1, const float* __restrict__ bm1,
                        const float* __restrict__ Wm2, const float* __restrict__ bm2,
                        float* __restrict__ out, int nrows) {
    extern __shared__ uint32_t smu[];
    uint32_t* WsT = smu;
    uint32_t* As  = smu + 128 * SOF;
    __shared__ float bs2[P];
    const int tid = threadIdx.x;
    const int row0 = blockIdx.x * 128;
    const int warp = tid >> 5, lane = tid & 31;
    const int wr = warp * 16;
    const int q = lane >> 2, p = lane & 3;

    load_w_tile(W2, WsT, 128);
    if (tid < P) bs2[tid] = bm2[tid];
    gather_rows_to_smem(efeat, As, g_noff, g_ncnt, g_npins, nrows, row0);
    __syncthreads();

    float acc[16][4];
    // ---- phase A: h2 = relu(A @ W2 + b2) ----
    mma_full(As, WsT, warp, lane, acc, 16);
    __syncthreads();
#pragma unroll
    for (int nf = 0; nf < 16; nf++) {
        int c = nf * 8 + 2 * p;
        float bx = __ldg(&b2[c]), by = __ldg(&b2[c + 1]);
        As[(wr + q) * SOF + nf * 4 + p] =
            packbf(fmaxf(acc[nf][0] + bx, 0.f), fmaxf(acc[nf][1] + by, 0.f));
        As[(wr + q + 8) * SOF + nf * 4 + p] =
            packbf(fmaxf(acc[nf][2] + bx, 0.f), fmaxf(acc[nf][3] + by, 0.f));
    }
    load_w_tile(Wm1, WsT, 128);
    __syncthreads();

    // ---- phase B: t = relu(h2 @ Wm1 + bm1) ----
    mma_full(As, WsT, warp, lane, acc, 16);
    __syncthreads();
#pragma unroll
    for (int nf = 0; nf < 16; nf++) {
        int c = nf * 8 + 2 * p;
        float bx = __ldg(&bm1[c]), by = __ldg(&bm1[c + 1]);
        As[(wr + q) * SOF + nf * 4 + p] =
            packbf(fmaxf(acc[nf][0] + bx, 0.f), fmaxf(acc[nf][1] + by, 0.f));
        As[(wr + q + 8) * SOF + nf * 4 + p] =
            packbf(fmaxf(acc[nf][2] + bx, 0.f), fmaxf(acc[nf][3] + by, 0.f));
    }
    load_w_tile(Wm2, WsT, 32);
    __syncthreads();

    // ---- phase C: logits = t @ Wm2 ----
    mma_full(As, WsT, warp, lane, acc, 4);

    // ---- softmax over 32 cols ----
    float vlo[8], vhi[8];
#pragma unroll
    for (int nf = 0; nf < 4; nf++) {
        int c = nf * 8 + 2 * p;
        vlo[nf * 2]     = acc[nf][0] + bs2[c];
        vlo[nf * 2 + 1] = acc[nf][1] + bs2[c + 1];
        vhi[nf * 2]     = acc[nf][2] + bs2[c];
        vhi[nf * 2 + 1] = acc[nf][3] + bs2[c + 1];
    }
    float mlo = vlo[0], mhi = vhi[0];
#pragma unroll
    for (int j = 1; j < 8; j++) { mlo = fmaxf(mlo, vlo[j]); mhi = fmaxf(mhi, vhi[j]); }
    mlo = fmaxf(mlo, __shfl_xor_sync(0xffffffffu, mlo, 1));
    mlo = fmaxf(mlo, __shfl_xor_sync(0xffffffffu, mlo, 2));
    mhi = fmaxf(mhi, __shfl_xor_sync(0xffffffffu, mhi, 1));
    mhi = fmaxf(mhi, __shfl_xor_sync(0xffffffffu, mhi, 2));
    float slo = 0.f, shi = 0.f;
#pragma unroll
    for (int j = 0; j < 8; j++) {
        vlo[j] = __expf(vlo[j] - mlo); slo += vlo[j];
        vhi[j] = __expf(vhi[j] - mhi); shi += vhi[j];
    }
    slo += __shfl_xor_sync(0xffffffffu, slo, 1);
    slo += __shfl_xor_sync(0xffffffffu, slo, 2);
    shi += __shfl_xor_sync(0xffffffffu, shi, 1);
    shi += __shfl_xor_sync(0xffffffffu, shi, 2);
    float rlo = 1.f / slo, rhi = 1.f / shi;

    int r_lo = row0 + wr + q;
    int r_hi = r_lo + 8;
#pragma unroll
    for (int nf = 0; nf < 4; nf++) {
        int c = nf * 8 + 2 * p;
        if (r_lo < nrows)
            *(float2*)&out[(size_t)r_lo * P + c] =
                make_float2(vlo[nf * 2] * rlo, vlo[nf * 2 + 1] * rlo);
        if (r_hi < nrows)
            *(float2*)&out[(size_t)r_hi * P + c] =
                make_float2(vhi[nf * 2] * rhi, vhi[nf * 2 + 1] * rhi);
    }
}

// ---------------- launch ------------------------------------------------------
extern "C" void kernel_launch(void* const* d_in, const int* in_sizes, int n_in,
                              void* d_out, int out_size) {
    const float* x   = (const float*)d_in[0];
    const int*   ni  = (const int*)  d_in[1];
    const int*   ei  = (const int*)  d_in[2];
    const float* W1  = (const float*)d_in[3];
    const float* b1  = (const float*)d_in[4];
    const float* W2  = (const float*)d_in[5];
    const float* b2  = (const float*)d_in[6];
    const float* Wm1 = (const float*)d_in[7];
    const float* bm1 = (const float*)d_in[8];
    const float* Wm2 = (const float*)d_in[9];
    const float* bm2 = (const float*)d_in[10];
    float* out = (float*)d_out;
    (void)in_sizes; (void)n_in; (void)out_size;

    cudaFuncSetAttribute(ngather_gemm_kernel,
                         cudaFuncAttributeMaxDynamicSharedMemorySize, SMEM_BYTES);
    cudaFuncSetAttribute(ngather_gemm_mlp_kernel,
                         cudaFuncAttributeMaxDynamicSharedMemorySize, SMEM_BYTES);

    __nv_bfloat16* xb;    cudaGetSymbolAddress((void**)&xb,    g_xb);
    __nv_bfloat16* efeat; cudaGetSymbolAddress((void**)&efeat, g_efeat);
    __nv_bfloat16* h1;    cudaGetSymbolAddress((void**)&h1,    g_h1);
    int* ecnt;  cudaGetSymbolAddress((void**)&ecnt,  g_ecnt);
    int* eoff;  cudaGetSymbolAddress((void**)&eoff,  g_eoff);
    int* epins; cudaGetSymbolAddress((void**)&epins, g_epins);

    // ---- CSR build + x conversion ----
    zf_kernel<<<2048, 256>>>(x);
    count_kernel<<<(NNZV + 255) / 256, 256>>>(ni, ei);
    scan_block_kernel<<<EBLK + NBLK, 256>>>();
    scan_sums_kernel<<<2, 256>>>();
    scan_add_kernel<<<(NE + NN + 255) / 256, 256>>>();
    fill_kernel<<<(NNZV + 255) / 256, 256>>>(ni, ei);

    const int egrid = (NE + 7) / 8;
    const int ggrid = (NN + 127) / 128;

    // ---- hconv layer 1 ----
    seg_mean_gather_kernel<<<egrid, 256>>>(xb, efeat, eoff, ecnt, epins, NE);
    ngather_gemm_kernel<<<ggrid, 256, SMEM_BYTES>>>(efeat, W1, b1, h1, NN);

    // ---- hconv layer 2 + MLP + softmax ----
    seg_mean_gather_kernel<<<egrid, 256>>>(h1, efeat, eoff, ecnt, epins, NE);
    ngather_gemm_mlp_kernel<<<ggrid, 256, SMEM_BYTES>>>(
        efeat, W2, b2, Wm1, bm1, Wm2, bm2, out, NN);
}